// round 4
// baseline (speedup 1.0000x reference)
#include <cuda_runtime.h>
#include <math.h>

// Problem dims
#define T_    512
#define B_    64
#define F_    256
#define E_    512
#define G4E   2048   // 4*E
#define G4F   1024   // 4*F
#define DECIN 1024   // 2*E

typedef unsigned long long u64;

// ---------------- device scratch (static; no allocations) ----------------
__device__ float g_xproj[2][T_][B_][G4E];     // [dir][t][b][col], col = u*4+gate
__device__ float g_WihIl[2][G4E][F_];         // interleaved enc Wih (rows = u*4+g)
__device__ float g_bIl[2][G4E];
__device__ u64   g_WhhDup[2][E_][E_][4];      // [dir][u][k][gate], each value duplicated {w,w}
__device__ float g_h[2][2][E_][B_];           // [dir][phase][u][b]  ping-pong
__device__ float g_WdecIhIl[F_][DECIN][4];    // [f][k][gate]
__device__ float g_bdecIl[F_][4];
__device__ u64   g_WdecHhDup[F_][F_][4];      // [f][k][gate] duplicated
__device__ float g_xp0[B_][F_][4];            // decoder constant input proj
__device__ float g_hd[2][F_][B_];             // decoder h ping-pong
__device__ unsigned g_flag_enc[128];
__device__ unsigned g_flag_dec[64];

__device__ __forceinline__ float sigm(float x) { return 1.0f / (1.0f + expf(-x)); }

__device__ __forceinline__ u64 dup2(float x) {
    u64 r; asm("mov.b64 %0, {%1, %1};" : "=l"(r) : "f"(x)); return r;
}
__device__ __forceinline__ void fma2(u64& d, u64 a, u64 b) {
    asm("fma.rn.f32x2 %0, %1, %2, %0;" : "+l"(d) : "l"(a), "l"(b));
}
__device__ __forceinline__ u64 add2(u64 a, u64 b) {
    u64 r; asm("add.rn.f32x2 %0, %1, %2;" : "=l"(r) : "l"(a), "l"(b)); return r;
}
__device__ __forceinline__ float2 unpk(u64 v) {
    float2 r; asm("mov.b64 {%0, %1}, %2;" : "=f"(r.x), "=f"(r.y) : "l"(v)); return r;
}
__device__ __forceinline__ void st_release(unsigned* p, unsigned v) {
    asm volatile("st.release.gpu.global.u32 [%0], %1;" :: "l"(p), "r"(v) : "memory");
}
__device__ __forceinline__ unsigned ld_acquire(unsigned* p) {
    unsigned v;
    asm volatile("ld.acquire.gpu.global.u32 %0, [%1];" : "=r"(v) : "l"(p) : "memory");
    return v;
}
__device__ __forceinline__ void cp16(void* sdst, const void* gsrc) {
    unsigned s = (unsigned)__cvta_generic_to_shared(sdst);
    asm volatile("cp.async.cg.shared.global [%0], [%1], 16;" :: "r"(s), "l"(gsrc) : "memory");
}
__device__ __forceinline__ void cp_commit() { asm volatile("cp.async.commit_group;" ::: "memory"); }
template<int N> __device__ __forceinline__ void cp_wait() {
    asm volatile("cp.async.wait_group %0;" :: "n"(N) : "memory");
}

// ---------------- prep: interleave + duplicate weights, zero states ----------------
__global__ void prep_kernel(const float* wihf, const float* whhf, const float* bf,
                            const float* wihb, const float* whhb, const float* bb,
                            const float* dwih, const float* dwhh, const float* db)
{
    int tid = blockIdx.x * blockDim.x + threadIdx.x;
    int stride = gridDim.x * blockDim.x;

    // enc Wih interleave: [2][2048][256]
    for (int i = tid; i < 2 * G4E * F_; i += stride) {
        int d = i / (G4E * F_);
        int r = i - d * (G4E * F_);
        int col = r / F_;
        int k = r - col * F_;
        int u = col >> 2, g = col & 3;
        const float* src = d ? wihb : wihf;
        g_WihIl[d][col][k] = src[(g * E_ + u) * F_ + k];
    }
    // enc bias interleave
    for (int i = tid; i < 2 * G4E; i += stride) {
        int d = i >> 11, col = i & (G4E - 1);
        int u = col >> 2, g = col & 3;
        g_bIl[d][col] = (d ? bb : bf)[g * E_ + u];
    }
    // enc Whh duplicated: [2][512][512][4] u64
    for (int i = tid; i < 2 * E_ * E_ * 4; i += stride) {
        int d = i / (E_ * E_ * 4);
        int r = i - d * (E_ * E_ * 4);
        int u = r / (E_ * 4);
        int k = (r >> 2) & (E_ - 1);
        int g = r & 3;
        float v = (d ? whhb : whhf)[(g * E_ + u) * E_ + k];
        unsigned bits = __float_as_uint(v);
        g_WhhDup[d][u][k][g] = ((u64)bits << 32) | (u64)bits;
    }
    // dec Wih interleave: [256][1024][4]
    for (int i = tid; i < F_ * DECIN * 4; i += stride) {
        int f = i / (DECIN * 4);
        int k = (i >> 2) & (DECIN - 1);
        int g = i & 3;
        g_WdecIhIl[f][k][g] = dwih[(g * F_ + f) * DECIN + k];
    }
    for (int i = tid; i < G4F; i += stride) {
        int f = i >> 2, g = i & 3;
        g_bdecIl[f][g] = db[g * F_ + f];
    }
    // dec Whh duplicated: [256][256][4] u64
    for (int i = tid; i < F_ * F_ * 4; i += stride) {
        int f = i / (F_ * 4);
        int k = (i >> 2) & (F_ - 1);
        int g = i & 3;
        float v = dwhh[(g * F_ + f) * F_ + k];
        unsigned bits = __float_as_uint(v);
        g_WdecHhDup[f][k][g] = ((u64)bits << 32) | (u64)bits;
    }
    // zero states + flags
    for (int i = tid; i < 2 * 2 * E_ * B_; i += stride) ((float*)g_h)[i] = 0.0f;
    for (int i = tid; i < 2 * F_ * B_; i += stride)     ((float*)g_hd)[i] = 0.0f;
    if (tid < 128) g_flag_enc[tid] = 0u;
    if (tid < 64)  g_flag_dec[tid] = 0u;
}

// ---------------- xproj GEMM: M=32768, N=2048, K=256 (A dup'd in smem) ----------------
// BM=128, BN=128, BK=16, 256 threads, per-thread 8m x 8n (n = tx*4 and tx*4+64).
__global__ void __launch_bounds__(256, 1) xproj_gemm(const float* __restrict__ seq)
{
    const int dir = blockIdx.z;
    const int m0 = blockIdx.y * 128;
    const int n0 = blockIdx.x * 128;
    const int tid = threadIdx.x;
    const int ty = tid >> 4;   // 0..15 -> rows ty*8..
    const int tx = tid & 15;   // 0..15 -> cols tx*4, tx*4+64

    __shared__ u64   As[16][128];   // duplicated A values
    __shared__ float Bs[16][128];

    u64 acc[8][4];
#pragma unroll
    for (int i = 0; i < 8; i++)
#pragma unroll
        for (int j = 0; j < 4; j++) acc[i][j] = 0ull;

    const float* W = &g_WihIl[dir][0][0];

    for (int k0 = 0; k0 < F_; k0 += 16) {
        // A tile: 128 rows x 16 k, duplicated stores
#pragma unroll
        for (int p = 0; p < 2; p++) {
            int idx = tid + p * 256;
            int row = idx >> 2, kq = idx & 3;
            int m = m0 + row;
            int tt = m >> 6, b = m & 63;
            int ts = dir ? (T_ - 1 - tt) : tt;
            float4 v = *(const float4*)&seq[((size_t)ts * B_ + b) * F_ + k0 + kq * 4];
            As[kq * 4 + 0][row] = dup2(v.x);
            As[kq * 4 + 1][row] = dup2(v.y);
            As[kq * 4 + 2][row] = dup2(v.z);
            As[kq * 4 + 3][row] = dup2(v.w);
        }
        // B tile: 128 n-rows x 16 k
#pragma unroll
        for (int p = 0; p < 2; p++) {
            int idx = tid + p * 256;
            int n = idx >> 2, kq = idx & 3;
            float4 v = *(const float4*)&W[(size_t)(n0 + n) * F_ + k0 + kq * 4];
            Bs[kq * 4 + 0][n] = v.x;
            Bs[kq * 4 + 1][n] = v.y;
            Bs[kq * 4 + 2][n] = v.z;
            Bs[kq * 4 + 3][n] = v.w;
        }
        __syncthreads();
#pragma unroll
        for (int kk = 0; kk < 16; kk++) {
            u64 a[8];
#pragma unroll
            for (int i = 0; i < 8; i++) a[i] = As[kk][ty * 8 + i];
            ulonglong2 bA = *(const ulonglong2*)&Bs[kk][tx * 4];
            ulonglong2 bB = *(const ulonglong2*)&Bs[kk][64 + tx * 4];
#pragma unroll
            for (int i = 0; i < 8; i++) {
                fma2(acc[i][0], a[i], bA.x);
                fma2(acc[i][1], a[i], bA.y);
                fma2(acc[i][2], a[i], bB.x);
                fma2(acc[i][3], a[i], bB.y);
            }
        }
        __syncthreads();
    }

    float4 bias0 = *(const float4*)&g_bIl[dir][n0 + tx * 4];
    float4 bias1 = *(const float4*)&g_bIl[dir][n0 + 64 + tx * 4];
    float* out = &g_xproj[0][0][0][0];
#pragma unroll
    for (int i = 0; i < 8; i++) {
        size_t m = (size_t)m0 + ty * 8 + i;
        size_t base = ((size_t)dir * 32768 + m) * (size_t)G4E + n0;
        float2 c0 = unpk(acc[i][0]), c1 = unpk(acc[i][1]);
        float2 c2 = unpk(acc[i][2]), c3 = unpk(acc[i][3]);
        float4 o0 = {c0.x + bias0.x, c0.y + bias0.y, c1.x + bias0.z, c1.y + bias0.w};
        float4 o1 = {c2.x + bias1.x, c2.y + bias1.y, c3.x + bias1.z, c3.y + bias1.w};
        *(float4*)&out[base + tx * 4] = o0;
        *(float4*)&out[base + 64 + tx * 4] = o1;
    }
}

// ---------------- persistent encoder ----------------
// 128 CTAs (64/dir, 8 units each), 256 threads: gate-split (G0: i,f; G1: g,o).
// smem: ws_dup 128KB (once) + hs 2x32KB chunks (cp.async pipeline) + xch 4KB.
__global__ void __launch_bounds__(256, 1) enc_persist()
{
    extern __shared__ char smraw[];
    u64*   wsd = (u64*)smraw;                       // [8][512][4] u64 = 131072 B
    float* hs  = (float*)(smraw + 131072);          // [2][128][64]  =  65536 B
    u64*   xch = (u64*)(smraw + 196608);            // [128][4]      =   4096 B

    const int dir = (int)(blockIdx.x >> 6);
    const int u0  = (int)(blockIdx.x & 63) * 8;
    const int tid = threadIdx.x;
    const int G   = tid >> 7;          // 0: gates i,f ; 1: gates g,o
    const int s   = tid & 127;
    const int uu  = s >> 4;
    const int b0  = (s & 15) * 4;
    const int u   = u0 + uu;

    // load duplicated Whh slice once (contiguous)
    {
        const float4* src = (const float4*)&g_WhhDup[dir][u0][0][0];  // 8192 float4
        float4* dst = (float4*)wsd;
        for (int i = tid; i < 8192; i += 256) dst[i] = src[i];
    }
    __syncthreads();

    const u64* wp0 = wsd + uu * 2048 + G * 2;   // [uu][k][gate], k stride 4 u64
    float c0 = 0.f, c1 = 0.f, c2 = 0.f, c3 = 0.f;

    for (int t = 0; t < T_; t++) {
        const int ph = t & 1;
        const char* hbase = (const char*)&g_h[dir][ph][0][0];

        float4 xpa, xpb, xpc, xpd;
        if (G == 0) {
            xpa = *(const float4*)&g_xproj[dir][t][b0 + 0][u << 2];
            xpb = *(const float4*)&g_xproj[dir][t][b0 + 1][u << 2];
            xpc = *(const float4*)&g_xproj[dir][t][b0 + 2][u << 2];
            xpd = *(const float4*)&g_xproj[dir][t][b0 + 3][u << 2];
        }

        // stage chunk 0
        {
            char* dst = (char*)hs;
            for (int i = tid; i < 2048; i += 256) cp16(dst + i * 16, hbase + i * 16);
            cp_commit();
        }

        u64 a0 = 0, a1 = 0, a2 = 0, a3 = 0;
        for (int kc = 0; kc < 4; kc++) {
            if (kc < 3) {   // stage next chunk into alternate buffer
                const char* src = hbase + (size_t)(kc + 1) * 32768;
                char* dst = (char*)hs + (size_t)((kc + 1) & 1) * 32768;
                for (int i = tid; i < 2048; i += 256) cp16(dst + i * 16, src + i * 16);
                cp_commit();
                cp_wait<1>();
            } else {
                cp_wait<0>();
            }
            __syncthreads();
            const float* hb = hs + (kc & 1) * 8192 + b0;
            const u64* wp = wp0 + kc * 128 * 4;
#pragma unroll 8
            for (int k = 0; k < 128; k++) {
                ulonglong2 hv = *(const ulonglong2*)(hb + (k << 6));
                ulonglong2 wv = *(const ulonglong2*)(wp + (k << 2));
                fma2(a0, hv.x, wv.x);
                fma2(a1, hv.y, wv.x);
                fma2(a2, hv.x, wv.y);
                fma2(a3, hv.y, wv.y);
            }
            __syncthreads();
        }

        // gate exchange: G1 publishes g,o partials
        if (G == 1) {
            *(ulonglong2*)(xch + s * 4)     = make_ulonglong2(a0, a1);
            *(ulonglong2*)(xch + s * 4 + 2) = make_ulonglong2(a2, a3);
        }
        __syncthreads();
        if (G == 0) {
            ulonglong2 gg = *(const ulonglong2*)(xch + s * 4);
            ulonglong2 oo = *(const ulonglong2*)(xch + s * 4 + 2);
            float2 i01 = unpk(a0), i23 = unpk(a1);
            float2 f01 = unpk(a2), f23 = unpk(a3);
            float2 gA = unpk(gg.x), gB = unpk(gg.y);
            float2 oA = unpk(oo.x), oB = unpk(oo.y);
            float4 hv;
            { float ig = sigm(i01.x + xpa.x), fg = sigm(f01.x + xpa.y);
              float gv = tanhf(gA.x + xpa.z), og = sigm(oA.x + xpa.w);
              c0 = fg * c0 + ig * gv; hv.x = og * tanhf(c0); }
            { float ig = sigm(i01.y + xpb.x), fg = sigm(f01.y + xpb.y);
              float gv = tanhf(gA.y + xpb.z), og = sigm(oA.y + xpb.w);
              c1 = fg * c1 + ig * gv; hv.y = og * tanhf(c1); }
            { float ig = sigm(i23.x + xpc.x), fg = sigm(f23.x + xpc.y);
              float gv = tanhf(gB.x + xpc.z), og = sigm(oB.x + xpc.w);
              c2 = fg * c2 + ig * gv; hv.z = og * tanhf(c2); }
            { float ig = sigm(i23.y + xpd.x), fg = sigm(f23.y + xpd.y);
              float gv = tanhf(gB.y + xpd.z), og = sigm(oB.y + xpd.w);
              c3 = fg * c3 + ig * gv; hv.w = og * tanhf(c3); }
            *(float4*)&g_h[dir][ph ^ 1][u][b0] = hv;
        }
        __syncthreads();

        // distributed-flag grid barrier
        if (tid == 0) st_release(&g_flag_enc[blockIdx.x], (unsigned)(t + 1));
        const unsigned tgt = (unsigned)(t + 1);
        int done;
        do {
            int p = 1;
            if (tid < 128) p = (ld_acquire(&g_flag_enc[tid]) >= tgt);
            done = __syncthreads_and(p);
        } while (!done);
    }
}

// ---------------- decoder constant input projection ----------------
__global__ void __launch_bounds__(128) xp0_kernel()
{
    const int w = threadIdx.x >> 5;
    const int l = threadIdx.x & 31;
    const int f = blockIdx.x * 2 + (w >> 1);
    const int b = (w & 1) * 32 + l;

    __shared__ float hsx[64][64];
    __shared__ float wsx[2][64][4];

    float acc[4] = {0.0f, 0.0f, 0.0f, 0.0f};

    for (int k0 = 0; k0 < DECIN; k0 += 64) {
        const float* hsrc = (k0 < E_) ? &g_h[0][0][k0][0] : &g_h[1][0][k0 - E_][0];
        {
            const float4* src = (const float4*)hsrc;
            float4* dst = (float4*)hsx;
            for (int i = threadIdx.x; i < 1024; i += 128) dst[i] = src[i];
        }
        {
            int idx = threadIdx.x;
            int uu = idx >> 6, kk = idx & 63;
            ((float4*)wsx)[idx] = *(const float4*)&g_WdecIhIl[blockIdx.x * 2 + uu][k0 + kk][0];
        }
        __syncthreads();
#pragma unroll 16
        for (int kk = 0; kk < 64; kk++) {
            float hv = hsx[kk][b];
            float4 wv = *(const float4*)&wsx[w >> 1][kk][0];
            acc[0] += hv * wv.x; acc[1] += hv * wv.y;
            acc[2] += hv * wv.z; acc[3] += hv * wv.w;
        }
        __syncthreads();
    }

    float4 r;
    r.x = acc[0] + g_bdecIl[f][0];
    r.y = acc[1] + g_bdecIl[f][1];
    r.z = acc[2] + g_bdecIl[f][2];
    r.w = acc[3] + g_bdecIl[f][3];
    *(float4*)&g_xp0[b][f][0] = r;
}

// ---------------- persistent decoder ----------------
// 64 CTAs (4 f-units each), 256 threads: k-split(2) x gate-split(2) x 64 slots.
// smem: ws_dup 32KB + hs 64KB + red 4KB + xch 2KB.
__global__ void __launch_bounds__(256, 1) dec_persist(float* __restrict__ out)
{
    extern __shared__ char smraw[];
    u64*   wsd = (u64*)smraw;                    // [4][256][4] u64 = 32768 B
    float* hs  = (float*)(smraw + 32768);        // [256][64]       = 65536 B
    u64*   red = (u64*)(smraw + 98304);          // [128][4]        =  4096 B
    u64*   xch = (u64*)(smraw + 102400);         // [64][4]         =  2048 B

    const int tid = threadIdx.x;
    const int ks  = tid >> 7;          // k half
    const int G   = (tid >> 6) & 1;    // gate pair
    const int s   = tid & 63;
    const int uu  = s >> 4;
    const int b0  = (s & 15) * 4;
    const int f   = (int)blockIdx.x * 4 + uu;

    // load duplicated dec Whh slice once
    {
        const float4* src = (const float4*)&g_WdecHhDup[blockIdx.x * 4][0][0]; // 2048 float4
        float4* dst = (float4*)wsd;
        for (int i = tid; i < 2048; i += 256) dst[i] = src[i];
    }
    __syncthreads();

    const u64* wp0 = wsd + uu * 1024 + G * 2;
    float c0 = 0.f, c1 = 0.f, c2 = 0.f, c3 = 0.f;

    // constant input projection (loaded once; used by epilogue threads)
    float4 xpa, xpb, xpc, xpd;
    if (tid < 64) {
        xpa = *(const float4*)&g_xp0[b0 + 0][f][0];
        xpb = *(const float4*)&g_xp0[b0 + 1][f][0];
        xpc = *(const float4*)&g_xp0[b0 + 2][f][0];
        xpd = *(const float4*)&g_xp0[b0 + 3][f][0];
    }

    for (int t = 0; t < T_; t++) {
        const int ph = t & 1;
        // stage full h (64KB)
        {
            const char* src = (const char*)&g_hd[ph][0][0];
            char* dst = (char*)hs;
            for (int i = tid; i < 4096; i += 256) cp16(dst + i * 16, src + i * 16);
            cp_commit();
            cp_wait<0>();
        }
        __syncthreads();

        u64 a0 = 0, a1 = 0, a2 = 0, a3 = 0;
        const float* hb = hs + ks * 128 * 64 + b0;
        const u64* wp = wp0 + ks * 128 * 4;
#pragma unroll 8
        for (int k = 0; k < 128; k++) {
            ulonglong2 hv = *(const ulonglong2*)(hb + (k << 6));
            ulonglong2 wv = *(const ulonglong2*)(wp + (k << 2));
            fma2(a0, hv.x, wv.x);
            fma2(a1, hv.y, wv.x);
            fma2(a2, hv.x, wv.y);
            fma2(a3, hv.y, wv.y);
        }

        // k reduction: high half publishes
        if (ks == 1) {
            *(ulonglong2*)(red + (tid & 127) * 4)     = make_ulonglong2(a0, a1);
            *(ulonglong2*)(red + (tid & 127) * 4 + 2) = make_ulonglong2(a2, a3);
        }
        __syncthreads();
        if (ks == 0) {
            ulonglong2 r01 = *(const ulonglong2*)(red + tid * 4);
            ulonglong2 r23 = *(const ulonglong2*)(red + tid * 4 + 2);
            a0 = add2(a0, r01.x); a1 = add2(a1, r01.y);
            a2 = add2(a2, r23.x); a3 = add2(a3, r23.y);
            if (G == 1) {   // publish g,o gates
                *(ulonglong2*)(xch + s * 4)     = make_ulonglong2(a0, a1);
                *(ulonglong2*)(xch + s * 4 + 2) = make_ulonglong2(a2, a3);
            }
        }
        __syncthreads();
        if (tid < 64) {   // ks==0, G==0: i,f gates + epilogue
            ulonglong2 gg = *(const ulonglong2*)(xch + s * 4);
            ulonglong2 oo = *(const ulonglong2*)(xch + s * 4 + 2);
            float2 i01 = unpk(a0), i23 = unpk(a1);
            float2 f01 = unpk(a2), f23 = unpk(a3);
            float2 gA = unpk(gg.x), gB = unpk(gg.y);
            float2 oA = unpk(oo.x), oB = unpk(oo.y);
            float4 hv;
            { float ig = sigm(i01.x + xpa.x), fg = sigm(f01.x + xpa.y);
              float gv = tanhf(gA.x + xpa.z), og = sigm(oA.x + xpa.w);
              c0 = fg * c0 + ig * gv; hv.x = og * tanhf(c0); }
            { float ig = sigm(i01.y + xpb.x), fg = sigm(f01.y + xpb.y);
              float gv = tanhf(gA.y + xpb.z), og = sigm(oA.y + xpb.w);
              c1 = fg * c1 + ig * gv; hv.y = og * tanhf(c1); }
            { float ig = sigm(i23.x + xpc.x), fg = sigm(f23.x + xpc.y);
              float gv = tanhf(gB.x + xpc.z), og = sigm(oB.x + xpc.w);
              c2 = fg * c2 + ig * gv; hv.z = og * tanhf(c2); }
            { float ig = sigm(i23.y + xpd.x), fg = sigm(f23.y + xpd.y);
              float gv = tanhf(gB.y + xpd.z), og = sigm(oB.y + xpd.w);
              c3 = fg * c3 + ig * gv; hv.w = og * tanhf(c3); }
            *(float4*)&g_hd[ph ^ 1][f][b0] = hv;
            out[((size_t)t * B_ + b0 + 0) * F_ + f] = hv.x;
            out[((size_t)t * B_ + b0 + 1) * F_ + f] = hv.y;
            out[((size_t)t * B_ + b0 + 2) * F_ + f] = hv.z;
            out[((size_t)t * B_ + b0 + 3) * F_ + f] = hv.w;
        }
        __syncthreads();

        if (tid == 0) st_release(&g_flag_dec[blockIdx.x], (unsigned)(t + 1));
        const unsigned tgt = (unsigned)(t + 1);
        int done;
        do {
            int p = 1;
            if (tid < 64) p = (ld_acquire(&g_flag_dec[tid]) >= tgt);
            done = __syncthreads_and(p);
        } while (!done);
    }
}

// ---------------- launch: 5 graph nodes ----------------
extern "C" void kernel_launch(void* const* d_in, const int* in_sizes, int n_in,
                              void* d_out, int out_size)
{
    const float* seq  = (const float*)d_in[0];
    const float* wihf = (const float*)d_in[1];
    const float* whhf = (const float*)d_in[2];
    const float* bf   = (const float*)d_in[3];
    const float* wihb = (const float*)d_in[4];
    const float* whhb = (const float*)d_in[5];
    const float* bb   = (const float*)d_in[6];
    const float* dwih = (const float*)d_in[7];
    const float* dwhh = (const float*)d_in[8];
    const float* db   = (const float*)d_in[9];
    float* out = (float*)d_out;

    cudaFuncSetAttribute(enc_persist, cudaFuncAttributeMaxDynamicSharedMemorySize, 200704);
    cudaFuncSetAttribute(dec_persist, cudaFuncAttributeMaxDynamicSharedMemorySize, 104448);

    prep_kernel<<<1024, 256>>>(wihf, whhf, bf, wihb, whhb, bb, dwih, dwhh, db);

    dim3 g(G4E / 128, 32768 / 128, 2);
    xproj_gemm<<<g, 256>>>(seq);

    enc_persist<<<128, 256, 200704>>>();

    xp0_kernel<<<128, 128>>>();

    dec_persist<<<64, 256, 104448>>>(out);
}

// round 7
// speedup vs baseline: 1.1036x; 1.1036x over previous
#include <cuda_runtime.h>
#include <math.h>

// Problem dims
#define T_    512
#define B_    64
#define F_    256
#define E_    512
#define G4E   2048   // 4*E
#define G4F   1024   // 4*F
#define DECIN 1024   // 2*E

typedef unsigned long long u64;

// ---------------- device scratch (static; no allocations) ----------------
__device__ float g_xproj[2][T_][B_][G4E];     // [dir][t][b][col], col = u*4+gate
__device__ float g_WihIl[2][G4E][F_];         // interleaved enc Wih (rows = u*4+g)
__device__ float g_bIl[2][G4E];
__device__ float g_WhhIl[2][E_][E_][4];       // [dir][u][k][gate]  (float, for broadcast)
__device__ float g_h[2][2][E_][B_];           // [dir][phase][u][b]  ping-pong
__device__ float g_WdecIhIl[F_][DECIN][4];    // [f][k][gate]
__device__ float g_bdecIl[F_][4];
__device__ u64   g_WdecHhDup[F_][F_][4];      // [f][k][gate] duplicated {w,w}
__device__ float g_xp0[B_][F_][4];            // decoder constant input proj
__device__ float g_hd[2][F_][B_];             // decoder h ping-pong
__device__ unsigned g_flag_enc[128];          // [dir][64]
__device__ unsigned g_flag_dec[128];

__device__ __forceinline__ float sigm(float x) { return 1.0f / (1.0f + expf(-x)); }

__device__ __forceinline__ u64 dup2(float x) {
    u64 r; asm("mov.b64 %0, {%1, %1};" : "=l"(r) : "f"(x)); return r;
}
__device__ __forceinline__ void fma2(u64& d, u64 a, u64 b) {
    asm("fma.rn.f32x2 %0, %1, %2, %0;" : "+l"(d) : "l"(a), "l"(b));
}
__device__ __forceinline__ u64 add2(u64 a, u64 b) {
    u64 r; asm("add.rn.f32x2 %0, %1, %2;" : "=l"(r) : "l"(a), "l"(b)); return r;
}
__device__ __forceinline__ float2 unpk(u64 v) {
    float2 r; asm("mov.b64 {%0, %1}, %2;" : "=f"(r.x), "=f"(r.y) : "l"(v)); return r;
}
__device__ __forceinline__ void st_release(unsigned* p, unsigned v) {
    asm volatile("st.release.gpu.global.u32 [%0], %1;" :: "l"(p), "r"(v) : "memory");
}
__device__ __forceinline__ unsigned ld_acquire(unsigned* p) {
    unsigned v;
    asm volatile("ld.acquire.gpu.global.u32 %0, [%1];" : "=r"(v) : "l"(p) : "memory");
    return v;
}
__device__ __forceinline__ void cp16(void* sdst, const void* gsrc) {
    unsigned s = (unsigned)__cvta_generic_to_shared(sdst);
    asm volatile("cp.async.cg.shared.global [%0], [%1], 16;" :: "r"(s), "l"(gsrc) : "memory");
}
__device__ __forceinline__ void cp_commit() { asm volatile("cp.async.commit_group;" ::: "memory"); }
template<int N> __device__ __forceinline__ void cp_wait() {
    asm volatile("cp.async.wait_group %0;" :: "n"(N) : "memory");
}
__device__ __forceinline__ void bar_named(int id, int cnt) {
    asm volatile("bar.sync %0, %1;" :: "r"(id), "r"(cnt) : "memory");
}

// ---------------- prep: interleave weights, zero states ----------------
__global__ void prep_kernel(const float* wihf, const float* whhf, const float* bf,
                            const float* wihb, const float* whhb, const float* bb,
                            const float* dwih, const float* dwhh, const float* db)
{
    int tid = blockIdx.x * blockDim.x + threadIdx.x;
    int stride = gridDim.x * blockDim.x;

    // enc Wih interleave: [2][2048][256]
    for (int i = tid; i < 2 * G4E * F_; i += stride) {
        int d = i / (G4E * F_);
        int r = i - d * (G4E * F_);
        int col = r / F_;
        int k = r - col * F_;
        int u = col >> 2, g = col & 3;
        const float* src = d ? wihb : wihf;
        g_WihIl[d][col][k] = src[(g * E_ + u) * F_ + k];
    }
    // enc bias interleave
    for (int i = tid; i < 2 * G4E; i += stride) {
        int d = i >> 11, col = i & (G4E - 1);
        int u = col >> 2, g = col & 3;
        g_bIl[d][col] = (d ? bb : bf)[g * E_ + u];
    }
    // enc Whh interleave (float): [2][512][512][4]
    for (int i = tid; i < 2 * E_ * E_ * 4; i += stride) {
        int d = i / (E_ * E_ * 4);
        int r = i - d * (E_ * E_ * 4);
        int u = r / (E_ * 4);
        int k = (r >> 2) & (E_ - 1);
        int g = r & 3;
        g_WhhIl[d][u][k][g] = (d ? whhb : whhf)[(g * E_ + u) * E_ + k];
    }
    // dec Wih interleave: [256][1024][4]
    for (int i = tid; i < F_ * DECIN * 4; i += stride) {
        int f = i / (DECIN * 4);
        int k = (i >> 2) & (DECIN - 1);
        int g = i & 3;
        g_WdecIhIl[f][k][g] = dwih[(g * F_ + f) * DECIN + k];
    }
    for (int i = tid; i < G4F; i += stride) {
        int f = i >> 2, g = i & 3;
        g_bdecIl[f][g] = db[g * F_ + f];
    }
    // dec Whh duplicated: [256][256][4] u64
    for (int i = tid; i < F_ * F_ * 4; i += stride) {
        int f = i / (F_ * 4);
        int k = (i >> 2) & (F_ - 1);
        int g = i & 3;
        float v = dwhh[(g * F_ + f) * F_ + k];
        unsigned bits = __float_as_uint(v);
        g_WdecHhDup[f][k][g] = ((u64)bits << 32) | (u64)bits;
    }
    // zero states + flags
    for (int i = tid; i < 2 * 2 * E_ * B_; i += stride) ((float*)g_h)[i] = 0.0f;
    for (int i = tid; i < 2 * F_ * B_; i += stride)     ((float*)g_hd)[i] = 0.0f;
    if (tid < 128) { g_flag_enc[tid] = 0u; g_flag_dec[tid] = 0u; }
}

// ---------------- xproj GEMM: M=32768, N=2048, K=256 (A dup'd in smem) ----------------
__global__ void __launch_bounds__(256, 1) xproj_gemm(const float* __restrict__ seq)
{
    const int dir = blockIdx.z;
    const int m0 = blockIdx.y * 128;
    const int n0 = blockIdx.x * 128;
    const int tid = threadIdx.x;
    const int ty = tid >> 4;
    const int tx = tid & 15;

    __shared__ u64   As[16][128];
    __shared__ float Bs[16][128];

    u64 acc[8][4];
#pragma unroll
    for (int i = 0; i < 8; i++)
#pragma unroll
        for (int j = 0; j < 4; j++) acc[i][j] = 0ull;

    const float* W = &g_WihIl[dir][0][0];

    for (int k0 = 0; k0 < F_; k0 += 16) {
#pragma unroll
        for (int p = 0; p < 2; p++) {
            int idx = tid + p * 256;
            int row = idx >> 2, kq = idx & 3;
            int m = m0 + row;
            int tt = m >> 6, b = m & 63;
            int ts = dir ? (T_ - 1 - tt) : tt;
            float4 v = *(const float4*)&seq[((size_t)ts * B_ + b) * F_ + k0 + kq * 4];
            As[kq * 4 + 0][row] = dup2(v.x);
            As[kq * 4 + 1][row] = dup2(v.y);
            As[kq * 4 + 2][row] = dup2(v.z);
            As[kq * 4 + 3][row] = dup2(v.w);
        }
#pragma unroll
        for (int p = 0; p < 2; p++) {
            int idx = tid + p * 256;
            int n = idx >> 2, kq = idx & 3;
            float4 v = *(const float4*)&W[(size_t)(n0 + n) * F_ + k0 + kq * 4];
            Bs[kq * 4 + 0][n] = v.x;
            Bs[kq * 4 + 1][n] = v.y;
            Bs[kq * 4 + 2][n] = v.z;
            Bs[kq * 4 + 3][n] = v.w;
        }
        __syncthreads();
#pragma unroll
        for (int kk = 0; kk < 16; kk++) {
            u64 a[8];
#pragma unroll
            for (int i = 0; i < 8; i++) a[i] = As[kk][ty * 8 + i];
            ulonglong2 bA = *(const ulonglong2*)&Bs[kk][tx * 4];
            ulonglong2 bB = *(const ulonglong2*)&Bs[kk][64 + tx * 4];
#pragma unroll
            for (int i = 0; i < 8; i++) {
                fma2(acc[i][0], a[i], bA.x);
                fma2(acc[i][1], a[i], bA.y);
                fma2(acc[i][2], a[i], bB.x);
                fma2(acc[i][3], a[i], bB.y);
            }
        }
        __syncthreads();
    }

    float4 bias0 = *(const float4*)&g_bIl[dir][n0 + tx * 4];
    float4 bias1 = *(const float4*)&g_bIl[dir][n0 + 64 + tx * 4];
    float* out = &g_xproj[0][0][0][0];
#pragma unroll
    for (int i = 0; i < 8; i++) {
        size_t m = (size_t)m0 + ty * 8 + i;
        size_t base = ((size_t)dir * 32768 + m) * (size_t)G4E + n0;
        float2 c0 = unpk(acc[i][0]), c1 = unpk(acc[i][1]);
        float2 c2 = unpk(acc[i][2]), c3 = unpk(acc[i][3]);
        float4 o0 = {c0.x + bias0.x, c0.y + bias0.y, c1.x + bias0.z, c1.y + bias0.w};
        float4 o1 = {c2.x + bias1.x, c2.y + bias1.y, c3.x + bias1.z, c3.y + bias1.w};
        *(float4*)&out[base + tx * 4] = o0;
        *(float4*)&out[base + 64 + tx * 4] = o1;
    }
}

// ---------------- persistent encoder ----------------
// 128 CTAs (64/dir, 8 units each), 256 threads: 4-way k-split (64-thread groups).
// Group layout: s = tid&63; unit = (s>>5)*4 + (lane>>3); b0 = (lane&7)*8.
// smem: ws 64KB+pad (float, stride 2052) + hs 128KB + xch 24KB = ~216KB.
#define ENC_WS_F4_STRIDE 513   // float4 stride per unit (bank-staggered)
#define ENC_HS_OFF 65664       // 8*513*16 bytes
#define ENC_XCH_OFF (65664 + 131072)
#define ENC_SMEM (ENC_XCH_OFF + 24576)

__global__ void __launch_bounds__(256, 1) enc_persist()
{
    extern __shared__ char smraw[];
    float* ws = (float*)smraw;
    float* hs = (float*)(smraw + ENC_HS_OFF);
    u64*  xch = (u64*)(smraw + ENC_XCH_OFF);

    const int dir = (int)(blockIdx.x >> 6);
    const int u0  = (int)(blockIdx.x & 63) * 8;
    const int tid = threadIdx.x;
    const int ks  = tid >> 6;          // k-quarter 0..3
    const int s   = tid & 63;
    const int l   = tid & 31;
    const int uu  = ((s >> 5) << 2) | (l >> 3);   // 0..7
    const int u   = u0 + uu;
    const int b0  = (l & 7) * 8;       // 8 batches

    // load Whh slice once into padded smem
    {
        const float4* src = (const float4*)&g_WhhIl[dir][u0][0][0];  // 4096 float4
        for (int i = tid; i < 4096; i += 256) {
            int su = i >> 9, kq = i & 511;
            ((float4*)ws)[su * ENC_WS_F4_STRIDE + kq] = src[i];
        }
    }
    __syncthreads();

    const float4* wp4 = (const float4*)ws + uu * ENC_WS_F4_STRIDE;
    float c[8];
#pragma unroll
    for (int j = 0; j < 8; j++) c[j] = 0.0f;

    for (int t = 0; t < T_; t++) {
        const int ph = t & 1;
        const int kbase = ks * 128;

        // stage this group's k-quarter (2048 float4) in 2 pipelined halves
        {
            const float4* hsrc = (const float4*)&g_h[dir][ph][kbase][0];
            float4* hdst = (float4*)&hs[kbase * 64];
            for (int i = s; i < 1024; i += 64) cp16(hdst + i, hsrc + i);
            cp_commit();
            for (int i = s + 1024; i < 2048; i += 64) cp16(hdst + i, hsrc + i);
            cp_commit();
        }

        // prefetch xproj (ks0 only; consumed in epilogue)
        float4 xp[8];
        if (ks == 0) {
#pragma unroll
            for (int j = 0; j < 8; j++)
                xp[j] = *(const float4*)&g_xproj[dir][t][b0 + j][u << 2];
        }

        u64 acc[4][4];
#pragma unroll
        for (int g = 0; g < 4; g++)
#pragma unroll
            for (int p = 0; p < 4; p++) acc[g][p] = 0ull;

#pragma unroll
        for (int half = 0; half < 2; half++) {
            if (half == 0) cp_wait<1>(); else cp_wait<0>();
            bar_named(1 + ks, 64);
            const int kst = kbase + half * 64;
#pragma unroll 4
            for (int kk = 0; kk < 64; kk++) {
                const int k = kst + kk;
                float4 wv = wp4[k];
                u64 wi = dup2(wv.x), wf = dup2(wv.y), wg = dup2(wv.z), wo = dup2(wv.w);
                const ulonglong2* hp = (const ulonglong2*)(hs + k * 64 + b0);
                ulonglong2 hA = hp[0], hB = hp[1];
                fma2(acc[0][0], hA.x, wi); fma2(acc[0][1], hA.y, wi);
                fma2(acc[0][2], hB.x, wi); fma2(acc[0][3], hB.y, wi);
                fma2(acc[1][0], hA.x, wf); fma2(acc[1][1], hA.y, wf);
                fma2(acc[1][2], hB.x, wf); fma2(acc[1][3], hB.y, wf);
                fma2(acc[2][0], hA.x, wg); fma2(acc[2][1], hA.y, wg);
                fma2(acc[2][2], hB.x, wg); fma2(acc[2][3], hB.y, wg);
                fma2(acc[3][0], hA.x, wo); fma2(acc[3][1], hA.y, wo);
                fma2(acc[3][2], hB.x, wo); fma2(acc[3][3], hB.y, wo);
            }
        }
        __syncthreads();

        // k-split reduction: groups 1..3 publish
        if (ks > 0) {
            ulonglong2* dst = (ulonglong2*)(xch + ((ks - 1) * 64 + s) * 16);
#pragma unroll
            for (int g = 0; g < 4; g++) {
                dst[g * 2 + 0] = make_ulonglong2(acc[g][0], acc[g][1]);
                dst[g * 2 + 1] = make_ulonglong2(acc[g][2], acc[g][3]);
            }
        }
        __syncthreads();

        if (ks == 0) {
#pragma unroll
            for (int r = 0; r < 3; r++) {
                const ulonglong2* src = (const ulonglong2*)(xch + (r * 64 + s) * 16);
#pragma unroll
                for (int g = 0; g < 4; g++) {
                    ulonglong2 v0 = src[g * 2 + 0];
                    ulonglong2 v1 = src[g * 2 + 1];
                    acc[g][0] = add2(acc[g][0], v0.x);
                    acc[g][1] = add2(acc[g][1], v0.y);
                    acc[g][2] = add2(acc[g][2], v1.x);
                    acc[g][3] = add2(acc[g][3], v1.y);
                }
            }
            float iv[8], fv[8], gv[8], ov[8];
#pragma unroll
            for (int p = 0; p < 4; p++) {
                float2 a = unpk(acc[0][p]); iv[2*p] = a.x; iv[2*p+1] = a.y;
                float2 b = unpk(acc[1][p]); fv[2*p] = b.x; fv[2*p+1] = b.y;
                float2 d = unpk(acc[2][p]); gv[2*p] = d.x; gv[2*p+1] = d.y;
                float2 e = unpk(acc[3][p]); ov[2*p] = e.x; ov[2*p+1] = e.y;
            }
            float hv[8];
#pragma unroll
            for (int j = 0; j < 8; j++) {
                float ig = sigm(iv[j] + xp[j].x);
                float fg = sigm(fv[j] + xp[j].y);
                float gg = tanhf(gv[j] + xp[j].z);
                float og = sigm(ov[j] + xp[j].w);
                c[j] = fg * c[j] + ig * gg;
                hv[j] = og * tanhf(c[j]);
            }
            float* hout = &g_h[dir][ph ^ 1][u][b0];
            *(float4*)(hout)     = make_float4(hv[0], hv[1], hv[2], hv[3]);
            *(float4*)(hout + 4) = make_float4(hv[4], hv[5], hv[6], hv[7]);
        }
        __syncthreads();

        // per-dir distributed-flag grid barrier (with backoff in retry path)
        if (tid == 0) {
            __threadfence();
            st_release(&g_flag_enc[dir * 64 + (blockIdx.x & 63)], (unsigned)(t + 1));
        }
        const unsigned tgt = (unsigned)(t + 1);
        int done;
        do {
            int p = 1;
            if (tid < 64) p = (ld_acquire(&g_flag_enc[dir * 64 + tid]) >= tgt);
            done = __syncthreads_and(p);
            if (!done && tid == 0) __nanosleep(128);
        } while (!done);
    }
}

// ---------------- decoder constant input projection ----------------
__global__ void __launch_bounds__(128) xp0_kernel()
{
    const int w = threadIdx.x >> 5;
    const int l = threadIdx.x & 31;
    const int f = blockIdx.x * 2 + (w >> 1);
    const int b = (w & 1) * 32 + l;

    __shared__ float hsx[64][64];
    __shared__ float wsx[2][64][4];

    float acc[4] = {0.0f, 0.0f, 0.0f, 0.0f};

    for (int k0 = 0; k0 < DECIN; k0 += 64) {
        const float* hsrc = (k0 < E_) ? &g_h[0][0][k0][0] : &g_h[1][0][k0 - E_][0];
        {
            const float4* src = (const float4*)hsrc;
            float4* dst = (float4*)hsx;
            for (int i = threadIdx.x; i < 1024; i += 128) dst[i] = src[i];
        }
        {
            int idx = threadIdx.x;
            int uu = idx >> 6, kk = idx & 63;
            ((float4*)wsx)[idx] = *(const float4*)&g_WdecIhIl[blockIdx.x * 2 + uu][k0 + kk][0];
        }
        __syncthreads();
#pragma unroll 16
        for (int kk = 0; kk < 64; kk++) {
            float hv = hsx[kk][b];
            float4 wv = *(const float4*)&wsx[w >> 1][kk][0];
            acc[0] += hv * wv.x; acc[1] += hv * wv.y;
            acc[2] += hv * wv.z; acc[3] += hv * wv.w;
        }
        __syncthreads();
    }

    float4 r;
    r.x = acc[0] + g_bdecIl[f][0];
    r.y = acc[1] + g_bdecIl[f][1];
    r.z = acc[2] + g_bdecIl[f][2];
    r.w = acc[3] + g_bdecIl[f][3];
    *(float4*)&g_xp0[b][f][0] = r;
}

// ---------------- persistent decoder ----------------
// 128 CTAs (2 f-units each), 256 threads: 4-way k-split; warp = 1 unit (full-warp
// broadcast of dup'd weights), lane = 2 batches.
#define DEC_HS_OFF 16384
#define DEC_XCH_OFF (16384 + 65536)
#define DEC_SMEM (DEC_XCH_OFF + 6144)

__global__ void __launch_bounds__(256, 1) dec_persist(float* __restrict__ out)
{
    extern __shared__ char smraw[];
    u64*   wsd = (u64*)smraw;                 // [2][256][4] u64
    float* hs  = (float*)(smraw + DEC_HS_OFF);
    u64*   xch = (u64*)(smraw + DEC_XCH_OFF);

    const int tid = threadIdx.x;
    const int ks  = tid >> 6;          // k-quarter 0..3 (64 k each)
    const int s   = tid & 63;
    const int l   = tid & 31;
    const int uu  = s >> 5;            // unit within CTA (warp-uniform)
    const int b0  = l * 2;
    const int f   = (int)blockIdx.x * 2 + uu;

    // load duplicated dec Whh slice once
    {
        const float4* src = (const float4*)&g_WdecHhDup[blockIdx.x * 2][0][0];
        float4* dst = (float4*)wsd;
        for (int i = tid; i < 1024; i += 256) dst[i] = src[i];
    }
    __syncthreads();

    const u64* wp = wsd + uu * 1024;   // [k][4]
    float c0 = 0.f, c1 = 0.f;
    float4 xpA, xpB;
    if (ks == 0) {
        xpA = *(const float4*)&g_xp0[b0 + 0][f][0];
        xpB = *(const float4*)&g_xp0[b0 + 1][f][0];
    }

    for (int t = 0; t < T_; t++) {
        const int ph = t & 1;
        const int kbase = ks * 64;

        // stage this group's quarter (1024 float4) in 2 halves
        {
            const float4* hsrc = (const float4*)&g_hd[ph][kbase][0];
            float4* hdst = (float4*)&hs[kbase * 64];
            for (int i = s; i < 512; i += 64) cp16(hdst + i, hsrc + i);
            cp_commit();
            for (int i = s + 512; i < 1024; i += 64) cp16(hdst + i, hsrc + i);
            cp_commit();
        }

        u64 acc[4] = {0ull, 0ull, 0ull, 0ull};
#pragma unroll
        for (int half = 0; half < 2; half++) {
            if (half == 0) cp_wait<1>(); else cp_wait<0>();
            bar_named(1 + ks, 64);
            const int kst = kbase + half * 32;
#pragma unroll 8
            for (int kk = 0; kk < 32; kk++) {
                const int k = kst + kk;
                u64 h01 = *(const u64*)(hs + k * 64 + b0);
                const ulonglong2* wq = (const ulonglong2*)(wp + k * 4);
                ulonglong2 w_if = wq[0], w_go = wq[1];
                fma2(acc[0], h01, w_if.x);
                fma2(acc[1], h01, w_if.y);
                fma2(acc[2], h01, w_go.x);
                fma2(acc[3], h01, w_go.y);
            }
        }
        __syncthreads();

        if (ks > 0) {
            ulonglong2* dst = (ulonglong2*)(xch + ((ks - 1) * 64 + s) * 4);
            dst[0] = make_ulonglong2(acc[0], acc[1]);
            dst[1] = make_ulonglong2(acc[2], acc[3]);
        }
        __syncthreads();

        if (ks == 0) {
#pragma unroll
            for (int r = 0; r < 3; r++) {
                const ulonglong2* src = (const ulonglong2*)(xch + (r * 64 + s) * 4);
                ulonglong2 v0 = src[0], v1 = src[1];
                acc[0] = add2(acc[0], v0.x);
                acc[1] = add2(acc[1], v0.y);
                acc[2] = add2(acc[2], v1.x);
                acc[3] = add2(acc[3], v1.y);
            }
            float2 iv = unpk(acc[0]), fv = unpk(acc[1]);
            float2 gv = unpk(acc[2]), ov = unpk(acc[3]);
            float2 hv;
            { float ig = sigm(iv.x + xpA.x), fg = sigm(fv.x + xpA.y);
              float gg = tanhf(gv.x + xpA.z), og = sigm(ov.x + xpA.w);
              c0 = fg * c0 + ig * gg; hv.x = og * tanhf(c0); }
            { float ig = sigm(iv.y + xpB.x), fg = sigm(fv.y + xpB.y);
              float gg = tanhf(gv.y + xpB.z), og = sigm(ov.y + xpB.w);
              c1 = fg * c1 + ig * gg; hv.y = og * tanhf(c1); }
            *(float2*)&g_hd[ph ^ 1][f][b0] = hv;
            out[((size_t)t * B_ + b0 + 0) * F_ + f] = hv.x;
            out[((size_t)t * B_ + b0 + 1) * F_ + f] = hv.y;
        }
        __syncthreads();

        if (tid == 0) {
            __threadfence();
            st_release(&g_flag_dec[blockIdx.x], (unsigned)(t + 1));
        }
        const unsigned tgt = (unsigned)(t + 1);
        int done;
        do {
            int p = 1;
            if (tid < 128) p = (ld_acquire(&g_flag_dec[tid]) >= tgt);
            done = __syncthreads_and(p);
            if (!done && tid == 0) __nanosleep(128);
        } while (!done);
    }
}

// ---------------- launch: 5 graph nodes ----------------
extern "C" void kernel_launch(void* const* d_in, const int* in_sizes, int n_in,
                              void* d_out, int out_size)
{
    const float* seq  = (const float*)d_in[0];
    const float* wihf = (const float*)d_in[1];
    const float* whhf = (const float*)d_in[2];
    const float* bf   = (const float*)d_in[3];
    const float* wihb = (const float*)d_in[4];
    const float* whhb = (const float*)d_in[5];
    const float* bb   = (const float*)d_in[6];
    const float* dwih = (const float*)d_in[7];
    const float* dwhh = (const float*)d_in[8];
    const float* db   = (const float*)d_in[9];
    float* out = (float*)d_out;

    cudaFuncSetAttribute(enc_persist, cudaFuncAttributeMaxDynamicSharedMemorySize, ENC_SMEM);
    cudaFuncSetAttribute(dec_persist, cudaFuncAttributeMaxDynamicSharedMemorySize, DEC_SMEM);

    prep_kernel<<<1024, 256>>>(wihf, whhf, bf, wihb, whhb, bb, dwih, dwhh, db);

    dim3 g(G4E / 128, 32768 / 128, 2);
    xproj_gemm<<<g, 256>>>(seq);

    enc_persist<<<128, 256, ENC_SMEM>>>();

    xp0_kernel<<<128, 128>>>();

    dec_persist<<<128, 256, DEC_SMEM>>>(out);
}

// round 10
// speedup vs baseline: 1.2952x; 1.1736x over previous
#include <cuda_runtime.h>
#include <math.h>

// Problem dims
#define T_    512
#define B_    64
#define F_    256
#define E_    512
#define G4E   2048   // 4*E
#define G4F   1024   // 4*F
#define DECIN 1024   // 2*E

typedef unsigned long long u64;

// ---------------- device scratch (static; no allocations) ----------------
__device__ float g_xproj[2][T_][B_][G4E];     // [dir][t][b][col], col = u*4+gate
__device__ float g_WihIl[2][G4E][F_];         // interleaved enc Wih (rows = u*4+g)
__device__ float g_bIl[2][G4E];
__device__ float g_WhhIl[2][E_][E_][4];       // [dir][u][k][gate]
__device__ float g_h[2][2][E_][B_];           // [dir][phase][u][b]  ping-pong
__device__ float g_WdecIhIl[F_][DECIN][4];    // [f][k][gate]
__device__ float g_bdecIl[F_][4];
__device__ u64   g_WdecHhDup[F_][F_][4];      // [f][k][gate] duplicated {w,w}
__device__ float g_hd[2][F_][B_];             // decoder h ping-pong
__device__ unsigned g_cnt[2][32];             // enc barrier counters (padded per dir)
__device__ unsigned g_cntd[32];               // dec barrier counter

__device__ __forceinline__ float sigm(float x) {
    return __fdividef(1.0f, 1.0f + __expf(-x));
}
__device__ __forceinline__ float tanh_f(float x) {
    float ax = fabsf(x);
    float e = __expf(-2.0f * ax);
    float r = (1.0f - e) * __fdividef(1.0f, 1.0f + e);
    return copysignf(r, x);
}

__device__ __forceinline__ u64 dup2(float x) {
    u64 r; asm("mov.b64 %0, {%1, %1};" : "=l"(r) : "f"(x)); return r;
}
__device__ __forceinline__ void fma2(u64& d, u64 a, u64 b) {
    asm("fma.rn.f32x2 %0, %1, %2, %0;" : "+l"(d) : "l"(a), "l"(b));
}
__device__ __forceinline__ u64 add2(u64 a, u64 b) {
    u64 r; asm("add.rn.f32x2 %0, %1, %2;" : "=l"(r) : "l"(a), "l"(b)); return r;
}
__device__ __forceinline__ float2 unpk(u64 v) {
    float2 r; asm("mov.b64 {%0, %1}, %2;" : "=f"(r.x), "=f"(r.y) : "l"(v)); return r;
}
__device__ __forceinline__ unsigned ld_acquire(unsigned* p) {
    unsigned v;
    asm volatile("ld.acquire.gpu.global.u32 %0, [%1];" : "=r"(v) : "l"(p) : "memory");
    return v;
}
__device__ __forceinline__ void red_release(unsigned* p, unsigned v) {
    asm volatile("red.release.gpu.global.add.u32 [%0], %1;" :: "l"(p), "r"(v) : "memory");
}
__device__ __forceinline__ ulonglong2 ldcg16(const void* p) {
    ulonglong2 v;
    asm volatile("ld.global.cg.v2.u64 {%0, %1}, [%2];" : "=l"(v.x), "=l"(v.y) : "l"(p));
    return v;
}
__device__ __forceinline__ u64 ldcg8(const void* p) {
    u64 v;
    asm volatile("ld.global.cg.u64 %0, [%1];" : "=l"(v) : "l"(p));
    return v;
}

// ---------------- probe: shifts ncu's captured position onto enc_persist ----------------
__global__ void probe_kernel() {}

// ---------------- prep: interleave weights, zero states ----------------
__global__ void prep_kernel(const float* wihf, const float* whhf, const float* bf,
                            const float* wihb, const float* whhb, const float* bb,
                            const float* dwih, const float* dwhh, const float* db)
{
    int tid = blockIdx.x * blockDim.x + threadIdx.x;
    int stride = gridDim.x * blockDim.x;

    // enc Wih interleave: [2][2048][256]
    for (int i = tid; i < 2 * G4E * F_; i += stride) {
        int d = i / (G4E * F_);
        int r = i - d * (G4E * F_);
        int col = r / F_;
        int k = r - col * F_;
        int u = col >> 2, g = col & 3;
        const float* src = d ? wihb : wihf;
        g_WihIl[d][col][k] = src[(g * E_ + u) * F_ + k];
    }
    // enc bias interleave
    for (int i = tid; i < 2 * G4E; i += stride) {
        int d = i >> 11, col = i & (G4E - 1);
        int u = col >> 2, g = col & 3;
        g_bIl[d][col] = (d ? bb : bf)[g * E_ + u];
    }
    // enc Whh interleave: [2][512][512][4]
    for (int i = tid; i < 2 * E_ * E_ * 4; i += stride) {
        int d = i / (E_ * E_ * 4);
        int r = i - d * (E_ * E_ * 4);
        int u = r / (E_ * 4);
        int k = (r >> 2) & (E_ - 1);
        int g = r & 3;
        g_WhhIl[d][u][k][g] = (d ? whhb : whhf)[(g * E_ + u) * E_ + k];
    }
    // dec Wih interleave: [256][1024][4]
    for (int i = tid; i < F_ * DECIN * 4; i += stride) {
        int f = i / (DECIN * 4);
        int k = (i >> 2) & (DECIN - 1);
        int g = i & 3;
        g_WdecIhIl[f][k][g] = dwih[(g * F_ + f) * DECIN + k];
    }
    for (int i = tid; i < G4F; i += stride) {
        int f = i >> 2, g = i & 3;
        g_bdecIl[f][g] = db[g * F_ + f];
    }
    // dec Whh duplicated: [256][256][4] u64
    for (int i = tid; i < F_ * F_ * 4; i += stride) {
        int f = i / (F_ * 4);
        int k = (i >> 2) & (F_ - 1);
        int g = i & 3;
        float v = dwhh[(g * F_ + f) * F_ + k];
        unsigned bits = __float_as_uint(v);
        g_WdecHhDup[f][k][g] = ((u64)bits << 32) | (u64)bits;
    }
    // zero states + counters
    for (int i = tid; i < 2 * 2 * E_ * B_; i += stride) ((float*)g_h)[i] = 0.0f;
    for (int i = tid; i < 2 * F_ * B_; i += stride)     ((float*)g_hd)[i] = 0.0f;
    if (tid < 64) ((unsigned*)g_cnt)[tid] = 0u;
    if (tid < 32) g_cntd[tid] = 0u;
}

// ---------------- xproj GEMM: M=32768, N=2048, K=256 (A dup'd in smem) ----------------
__global__ void __launch_bounds__(256, 1) xproj_gemm(const float* __restrict__ seq)
{
    const int dir = blockIdx.z;
    const int m0 = blockIdx.y * 128;
    const int n0 = blockIdx.x * 128;
    const int tid = threadIdx.x;
    const int ty = tid >> 4;
    const int tx = tid & 15;

    __shared__ u64   As[16][128];
    __shared__ float Bs[16][128];

    u64 acc[8][4];
#pragma unroll
    for (int i = 0; i < 8; i++)
#pragma unroll
        for (int j = 0; j < 4; j++) acc[i][j] = 0ull;

    const float* W = &g_WihIl[dir][0][0];

    for (int k0 = 0; k0 < F_; k0 += 16) {
#pragma unroll
        for (int p = 0; p < 2; p++) {
            int idx = tid + p * 256;
            int row = idx >> 2, kq = idx & 3;
            int m = m0 + row;
            int tt = m >> 6, b = m & 63;
            int ts = dir ? (T_ - 1 - tt) : tt;
            float4 v = *(const float4*)&seq[((size_t)ts * B_ + b) * F_ + k0 + kq * 4];
            As[kq * 4 + 0][row] = dup2(v.x);
            As[kq * 4 + 1][row] = dup2(v.y);
            As[kq * 4 + 2][row] = dup2(v.z);
            As[kq * 4 + 3][row] = dup2(v.w);
        }
#pragma unroll
        for (int p = 0; p < 2; p++) {
            int idx = tid + p * 256;
            int n = idx >> 2, kq = idx & 3;
            float4 v = *(const float4*)&W[(size_t)(n0 + n) * F_ + k0 + kq * 4];
            Bs[kq * 4 + 0][n] = v.x;
            Bs[kq * 4 + 1][n] = v.y;
            Bs[kq * 4 + 2][n] = v.z;
            Bs[kq * 4 + 3][n] = v.w;
        }
        __syncthreads();
#pragma unroll
        for (int kk = 0; kk < 16; kk++) {
            u64 a[8];
#pragma unroll
            for (int i = 0; i < 8; i++) a[i] = As[kk][ty * 8 + i];
            ulonglong2 bA = *(const ulonglong2*)&Bs[kk][tx * 4];
            ulonglong2 bB = *(const ulonglong2*)&Bs[kk][64 + tx * 4];
#pragma unroll
            for (int i = 0; i < 8; i++) {
                fma2(acc[i][0], a[i], bA.x);
                fma2(acc[i][1], a[i], bA.y);
                fma2(acc[i][2], a[i], bB.x);
                fma2(acc[i][3], a[i], bB.y);
            }
        }
        __syncthreads();
    }

    float4 bias0 = *(const float4*)&g_bIl[dir][n0 + tx * 4];
    float4 bias1 = *(const float4*)&g_bIl[dir][n0 + 64 + tx * 4];
    float* out = &g_xproj[0][0][0][0];
#pragma unroll
    for (int i = 0; i < 8; i++) {
        size_t m = (size_t)m0 + ty * 8 + i;
        size_t base = ((size_t)dir * 32768 + m) * (size_t)G4E + n0;
        float2 c0 = unpk(acc[i][0]), c1 = unpk(acc[i][1]);
        float2 c2 = unpk(acc[i][2]), c3 = unpk(acc[i][3]);
        float4 o0 = {c0.x + bias0.x, c0.y + bias0.y, c1.x + bias0.z, c1.y + bias0.w};
        float4 o1 = {c2.x + bias1.x, c2.y + bias1.y, c3.x + bias1.z, c3.y + bias1.w};
        *(float4*)&out[base + tx * 4] = o0;
        *(float4*)&out[base + 64 + tx * 4] = o1;
    }
}

// ---------------- persistent encoder ----------------
// 128 CTAs (64/dir, 8 units each), 256 threads, 4-way k-split.
// h read directly via ld.global.cg (no smem staging). xch transposed (conflict-free).
#define ENC_WS_F4_STRIDE 513   // float4 stride per unit (bank-staggered)
#define ENC_XCH_OFF 65664      // 8*513*16 bytes
#define ENC_SMEM (ENC_XCH_OFF + 24576)

__global__ void __launch_bounds__(256, 1) enc_persist()
{
    extern __shared__ char smraw[];
    float* ws = (float*)smraw;
    u64*  xch = (u64*)(smraw + ENC_XCH_OFF);   // [3 groups][16 elems][64 slots]

    const int dir = (int)(blockIdx.x >> 6);
    const int u0  = (int)(blockIdx.x & 63) * 8;
    const int tid = threadIdx.x;
    const int ks  = tid >> 6;          // k-quarter 0..3
    const int s   = tid & 63;
    const int l   = tid & 31;
    const int uu  = ((s >> 5) << 2) | (l >> 3);
    const int u   = u0 + uu;
    const int b0  = (l & 7) * 8;

    // load Whh slice once into padded smem
    {
        const float4* src = (const float4*)&g_WhhIl[dir][u0][0][0];
        for (int i = tid; i < 4096; i += 256) {
            int su = i >> 9, kq = i & 511;
            ((float4*)ws)[su * ENC_WS_F4_STRIDE + kq] = src[i];
        }
    }
    __syncthreads();

    const float4* wp4 = (const float4*)ws + uu * ENC_WS_F4_STRIDE;
    unsigned* cnt = &g_cnt[dir][0];
    float c[8];
#pragma unroll
    for (int j = 0; j < 8; j++) c[j] = 0.0f;

    // prefetch xproj for t=0
    float4 xp[8];
    if (ks == 0) {
#pragma unroll
        for (int j = 0; j < 8; j++)
            xp[j] = *(const float4*)&g_xproj[dir][0][b0 + j][u << 2];
    }

    for (int t = 0; t < T_; t++) {
        const int ph = t & 1;

        // wait for h(t-1) from all CTAs of this dir
        if (t > 0) {
            if (tid < 32) {
                const unsigned tgt = (unsigned)t * 64u;
                while (ld_acquire(cnt) < tgt) {}
            }
            __syncthreads();
        }

        const float* hbase = &g_h[dir][ph][0][0];
        const int kbase = ks * 128;

        u64 acc[4][4];
#pragma unroll
        for (int g = 0; g < 4; g++)
#pragma unroll
            for (int p = 0; p < 4; p++) acc[g][p] = 0ull;

#pragma unroll 4
        for (int kk = 0; kk < 128; kk++) {
            const int k = kbase + kk;
            float4 wv = wp4[k];
            u64 wi = dup2(wv.x), wf = dup2(wv.y), wg = dup2(wv.z), wo = dup2(wv.w);
            const char* hp = (const char*)(hbase + k * 64 + b0);
            ulonglong2 hA = ldcg16(hp);
            ulonglong2 hB = ldcg16(hp + 16);
            fma2(acc[0][0], hA.x, wi); fma2(acc[0][1], hA.y, wi);
            fma2(acc[0][2], hB.x, wi); fma2(acc[0][3], hB.y, wi);
            fma2(acc[1][0], hA.x, wf); fma2(acc[1][1], hA.y, wf);
            fma2(acc[1][2], hB.x, wf); fma2(acc[1][3], hB.y, wf);
            fma2(acc[2][0], hA.x, wg); fma2(acc[2][1], hA.y, wg);
            fma2(acc[2][2], hB.x, wg); fma2(acc[2][3], hB.y, wg);
            fma2(acc[3][0], hA.x, wo); fma2(acc[3][1], hA.y, wo);
            fma2(acc[3][2], hB.x, wo); fma2(acc[3][3], hB.y, wo);
        }

        // publish partials (transposed layout: element-major, slot contiguous)
        if (ks > 0) {
            u64* dst = xch + (size_t)(ks - 1) * 16 * 64 + s;
#pragma unroll
            for (int g = 0; g < 4; g++)
#pragma unroll
                for (int p = 0; p < 4; p++)
                    dst[(g * 4 + p) * 64] = acc[g][p];
        }
        __syncthreads();

        if (ks == 0) {
            const u64* src0 = xch + s;
#pragma unroll
            for (int r = 0; r < 3; r++) {
                const u64* src = src0 + (size_t)r * 16 * 64;
#pragma unroll
                for (int g = 0; g < 4; g++)
#pragma unroll
                    for (int p = 0; p < 4; p++)
                        acc[g][p] = add2(acc[g][p], src[(g * 4 + p) * 64]);
            }
            float iv[8], fv[8], gv[8], ov[8];
#pragma unroll
            for (int p = 0; p < 4; p++) {
                float2 a = unpk(acc[0][p]); iv[2*p] = a.x; iv[2*p+1] = a.y;
                float2 b = unpk(acc[1][p]); fv[2*p] = b.x; fv[2*p+1] = b.y;
                float2 d = unpk(acc[2][p]); gv[2*p] = d.x; gv[2*p+1] = d.y;
                float2 e = unpk(acc[3][p]); ov[2*p] = e.x; ov[2*p+1] = e.y;
            }
            float hv[8];
#pragma unroll
            for (int j = 0; j < 8; j++) {
                float ig = sigm(iv[j] + xp[j].x);
                float fg = sigm(fv[j] + xp[j].y);
                float gg = tanh_f(gv[j] + xp[j].z);
                float og = sigm(ov[j] + xp[j].w);
                c[j] = fg * c[j] + ig * gg;
                hv[j] = og * tanh_f(c[j]);
            }
            float* hout = &g_h[dir][ph ^ 1][u][b0];
            *(float4*)(hout)     = make_float4(hv[0], hv[1], hv[2], hv[3]);
            *(float4*)(hout + 4) = make_float4(hv[4], hv[5], hv[6], hv[7]);
        }
        __syncthreads();

        // arrive, then overlap next-step xproj prefetch with barrier propagation
        if (tid == 0) red_release(cnt, 1u);
        if (ks == 0 && t + 1 < T_) {
#pragma unroll
            for (int j = 0; j < 8; j++)
                xp[j] = *(const float4*)&g_xproj[dir][t + 1][b0 + j][u << 2];
        }
    }
}

// ---------------- persistent decoder (xp0 fused) ----------------
// 128 CTAs (2 f-units each), 256 threads, 4-way k-split; h via ld.global.cg.
// smem: wsd 16KB + xch 6KB (transposed) + xp0s 2KB = 24.5KB.
#define DEC_XCH_OFF 16384
#define DEC_XP0_OFF (16384 + 6144)
#define DEC_SMEM (DEC_XP0_OFF + 2048)

__global__ void __launch_bounds__(256, 1) dec_persist(float* __restrict__ out)
{
    extern __shared__ char smraw[];
    u64*   wsd  = (u64*)smraw;                      // [2][256][4] u64
    u64*   xch  = (u64*)(smraw + DEC_XCH_OFF);      // [3][4][64] u64
    float* xp0s = (float*)(smraw + DEC_XP0_OFF);    // [64][2][4] floats

    const int tid = threadIdx.x;
    const int ks  = tid >> 6;          // k-quarter 0..3 (64 k each)
    const int s   = tid & 63;
    const int l   = tid & 31;
    const int uu  = s >> 5;            // unit within CTA (warp-uniform)
    const int b0  = l * 2;
    const int f   = (int)blockIdx.x * 2 + uu;

    // load duplicated dec Whh slice once
    {
        const float4* src = (const float4*)&g_WdecHhDup[blockIdx.x * 2][0][0];
        float4* dst = (float4*)wsd;
        for (int i = tid; i < 1024; i += 256) dst[i] = src[i];
    }

    // ---- fused xp0: thread = (f_local, gate-pair, batch) ----
    {
        const int fl = tid >> 7;            // 0..1
        const int gp = (tid >> 6) & 1;      // gate pair: 0 -> (i,f), 1 -> (g,o)
        const int b  = tid & 63;
        const int ff = (int)blockIdx.x * 2 + fl;
        float a0 = 0.0f, a1 = 0.0f;
        const float* wih = &g_WdecIhIl[ff][0][gp * 2];
#pragma unroll 4
        for (int k = 0; k < 512; k++) {
            float hv = __ldg(&g_h[0][0][k][b]);
            float2 w2 = *(const float2*)&wih[k * 4];
            a0 += hv * w2.x; a1 += hv * w2.y;
        }
#pragma unroll 4
        for (int k = 0; k < 512; k++) {
            float hv = __ldg(&g_h[1][0][k][b]);
            float2 w2 = *(const float2*)&wih[(512 + k) * 4];
            a0 += hv * w2.x; a1 += hv * w2.y;
        }
        xp0s[(b * 2 + fl) * 4 + gp * 2 + 0] = a0 + g_bdecIl[ff][gp * 2 + 0];
        xp0s[(b * 2 + fl) * 4 + gp * 2 + 1] = a1 + g_bdecIl[ff][gp * 2 + 1];
    }
    __syncthreads();

    const u64* wp = wsd + uu * 1024;   // [k][4]
    unsigned* cnt = g_cntd;
    float c0 = 0.f, c1 = 0.f;
    float4 xpA, xpB;
    if (ks == 0) {
        xpA = *(const float4*)&xp0s[(b0 * 2 + uu) * 4];
        xpB = *(const float4*)&xp0s[((b0 + 1) * 2 + uu) * 4];
    }

    for (int t = 0; t < T_; t++) {
        const int ph = t & 1;

        if (t > 0) {
            if (tid < 32) {
                const unsigned tgt = (unsigned)t * 128u;
                while (ld_acquire(cnt) < tgt) {}
            }
            __syncthreads();
        }

        const float* hbase = &g_hd[ph][0][0];
        const int kbase = ks * 64;

        u64 acc[4] = {0ull, 0ull, 0ull, 0ull};
#pragma unroll 8
        for (int kk = 0; kk < 64; kk++) {
            const int k = kbase + kk;
            u64 h01 = ldcg8(hbase + k * 64 + b0);
            const ulonglong2* wq = (const ulonglong2*)(wp + k * 4);
            ulonglong2 w_if = wq[0], w_go = wq[1];
            fma2(acc[0], h01, w_if.x);
            fma2(acc[1], h01, w_if.y);
            fma2(acc[2], h01, w_go.x);
            fma2(acc[3], h01, w_go.y);
        }

        if (ks > 0) {
            u64* dst = xch + (size_t)(ks - 1) * 4 * 64 + s;
            dst[0]       = acc[0];
            dst[64]      = acc[1];
            dst[128]     = acc[2];
            dst[192]     = acc[3];
        }
        __syncthreads();

        if (ks == 0) {
            const u64* src0 = xch + s;
#pragma unroll
            for (int r = 0; r < 3; r++) {
                const u64* src = src0 + (size_t)r * 4 * 64;
                acc[0] = add2(acc[0], src[0]);
                acc[1] = add2(acc[1], src[64]);
                acc[2] = add2(acc[2], src[128]);
                acc[3] = add2(acc[3], src[192]);
            }
            float2 iv = unpk(acc[0]), fv = unpk(acc[1]);
            float2 gv = unpk(acc[2]), ov = unpk(acc[3]);
            float2 hv;
            { float ig = sigm(iv.x + xpA.x), fg = sigm(fv.x + xpA.y);
              float gg = tanh_f(gv.x + xpA.z), og = sigm(ov.x + xpA.w);
              c0 = fg * c0 + ig * gg; hv.x = og * tanh_f(c0); }
            { float ig = sigm(iv.y + xpB.x), fg = sigm(fv.y + xpB.y);
              float gg = tanh_f(gv.y + xpB.z), og = sigm(ov.y + xpB.w);
              c1 = fg * c1 + ig * gg; hv.y = og * tanh_f(c1); }
            *(float2*)&g_hd[ph ^ 1][f][b0] = hv;
            out[((size_t)t * B_ + b0 + 0) * F_ + f] = hv.x;
            out[((size_t)t * B_ + b0 + 1) * F_ + f] = hv.y;
        }
        __syncthreads();

        if (tid == 0) red_release(cnt, 1u);
    }
}

// ---------------- launch: 5 graph nodes ----------------
extern "C" void kernel_launch(void* const* d_in, const int* in_sizes, int n_in,
                              void* d_out, int out_size)
{
    const float* seq  = (const float*)d_in[0];
    const float* wihf = (const float*)d_in[1];
    const float* whhf = (const float*)d_in[2];
    const float* bf   = (const float*)d_in[3];
    const float* wihb = (const float*)d_in[4];
    const float* whhb = (const float*)d_in[5];
    const float* bb   = (const float*)d_in[6];
    const float* dwih = (const float*)d_in[7];
    const float* dwhh = (const float*)d_in[8];
    const float* db   = (const float*)d_in[9];
    float* out = (float*)d_out;

    cudaFuncSetAttribute(enc_persist, cudaFuncAttributeMaxDynamicSharedMemorySize, ENC_SMEM);
    cudaFuncSetAttribute(dec_persist, cudaFuncAttributeMaxDynamicSharedMemorySize, DEC_SMEM);

    probe_kernel<<<1, 1>>>();

    prep_kernel<<<1024, 256>>>(wihf, whhf, bf, wihb, whhb, bb, dwih, dwhh, db);

    dim3 g(G4E / 128, 32768 / 128, 2);
    xproj_gemm<<<g, 256>>>(seq);

    enc_persist<<<128, 256, ENC_SMEM>>>();

    dec_persist<<<128, 256, DEC_SMEM>>>(out);
}

// round 11
// speedup vs baseline: 1.4977x; 1.1564x over previous
#include <cuda_runtime.h>
#include <math.h>

// Problem dims
#define T_    512
#define B_    64
#define F_    256
#define E_    512
#define G4E   2048   // 4*E
#define G4F   1024   // 4*F
#define DECIN 1024   // 2*E

typedef unsigned long long u64;

// ---------------- device scratch (static; no allocations) ----------------
__device__ float g_xproj[2][T_][B_][G4E];     // [dir][t][b][col], col = u*4+gate
__device__ float g_WihIl[2][G4E][F_];         // interleaved enc Wih (rows = u*4+g)
__device__ float g_bIl[2][G4E];
__device__ float g_WhhIl[2][E_][E_][4];       // [dir][u][k][gate]
__device__ float g_h[2][2][E_][B_];           // [dir][phase][u][b]  ping-pong
__device__ float g_WdecIhIl[F_][DECIN][4];    // [f][k][gate]
__device__ float g_bdecIl[F_][4];
__device__ u64   g_WdecHhDup[F_][F_][4];      // [f][k][gate] duplicated {w,w}
__device__ float g_hd[2][F_][B_];             // decoder h ping-pong
__device__ unsigned g_cnt[2][32];             // enc barrier counters (padded per dir)
__device__ unsigned g_cntd[32];               // dec barrier counter

__device__ __forceinline__ float sigm(float x) {
    return __fdividef(1.0f, 1.0f + __expf(-x));
}
__device__ __forceinline__ float tanh_f(float x) {
    float ax = fabsf(x);
    float e = __expf(-2.0f * ax);
    float r = (1.0f - e) * __fdividef(1.0f, 1.0f + e);
    return copysignf(r, x);
}

__device__ __forceinline__ u64 dup2(float x) {
    u64 r; asm("mov.b64 %0, {%1, %1};" : "=l"(r) : "f"(x)); return r;
}
__device__ __forceinline__ void fma2(u64& d, u64 a, u64 b) {
    asm("fma.rn.f32x2 %0, %1, %2, %0;" : "+l"(d) : "l"(a), "l"(b));
}
__device__ __forceinline__ u64 add2(u64 a, u64 b) {
    u64 r; asm("add.rn.f32x2 %0, %1, %2;" : "=l"(r) : "l"(a), "l"(b)); return r;
}
__device__ __forceinline__ float2 unpk(u64 v) {
    float2 r; asm("mov.b64 {%0, %1}, %2;" : "=f"(r.x), "=f"(r.y) : "l"(v)); return r;
}
__device__ __forceinline__ unsigned ld_acquire(unsigned* p) {
    unsigned v;
    asm volatile("ld.acquire.gpu.global.u32 %0, [%1];" : "=r"(v) : "l"(p) : "memory");
    return v;
}
__device__ __forceinline__ void red_release(unsigned* p, unsigned v) {
    asm volatile("red.release.gpu.global.add.u32 [%0], %1;" :: "l"(p), "r"(v) : "memory");
}
__device__ __forceinline__ u64 ldcg8(const void* p) {
    u64 v;
    asm volatile("ld.global.cg.u64 %0, [%1];" : "=l"(v) : "l"(p));
    return v;
}
__device__ __forceinline__ void cp16(void* sdst, const void* gsrc) {
    unsigned s = (unsigned)__cvta_generic_to_shared(sdst);
    asm volatile("cp.async.cg.shared.global [%0], [%1], 16;" :: "r"(s), "l"(gsrc) : "memory");
}
__device__ __forceinline__ void cp_commit() { asm volatile("cp.async.commit_group;" ::: "memory"); }
template<int N> __device__ __forceinline__ void cp_wait() {
    asm volatile("cp.async.wait_group %0;" :: "n"(N) : "memory");
}
__device__ __forceinline__ void bar_named(int id, int cnt) {
    asm volatile("bar.sync %0, %1;" :: "r"(id), "r"(cnt) : "memory");
}

// ---------------- probe: keeps ncu's captured position on enc_persist ----------------
__global__ void probe_kernel() {}

// ---------------- prep: interleave weights, zero states ----------------
__global__ void prep_kernel(const float* wihf, const float* whhf, const float* bf,
                            const float* wihb, const float* whhb, const float* bb,
                            const float* dwih, const float* dwhh, const float* db)
{
    int tid = blockIdx.x * blockDim.x + threadIdx.x;
    int stride = gridDim.x * blockDim.x;

    // enc Wih interleave: [2][2048][256]
    for (int i = tid; i < 2 * G4E * F_; i += stride) {
        int d = i / (G4E * F_);
        int r = i - d * (G4E * F_);
        int col = r / F_;
        int k = r - col * F_;
        int u = col >> 2, g = col & 3;
        const float* src = d ? wihb : wihf;
        g_WihIl[d][col][k] = src[(g * E_ + u) * F_ + k];
    }
    // enc bias interleave
    for (int i = tid; i < 2 * G4E; i += stride) {
        int d = i >> 11, col = i & (G4E - 1);
        int u = col >> 2, g = col & 3;
        g_bIl[d][col] = (d ? bb : bf)[g * E_ + u];
    }
    // enc Whh interleave: [2][512][512][4]
    for (int i = tid; i < 2 * E_ * E_ * 4; i += stride) {
        int d = i / (E_ * E_ * 4);
        int r = i - d * (E_ * E_ * 4);
        int u = r / (E_ * 4);
        int k = (r >> 2) & (E_ - 1);
        int g = r & 3;
        g_WhhIl[d][u][k][g] = (d ? whhb : whhf)[(g * E_ + u) * E_ + k];
    }
    // dec Wih interleave: [256][1024][4]
    for (int i = tid; i < F_ * DECIN * 4; i += stride) {
        int f = i / (DECIN * 4);
        int k = (i >> 2) & (DECIN - 1);
        int g = i & 3;
        g_WdecIhIl[f][k][g] = dwih[(g * F_ + f) * DECIN + k];
    }
    for (int i = tid; i < G4F; i += stride) {
        int f = i >> 2, g = i & 3;
        g_bdecIl[f][g] = db[g * F_ + f];
    }
    // dec Whh duplicated: [256][256][4] u64
    for (int i = tid; i < F_ * F_ * 4; i += stride) {
        int f = i / (F_ * 4);
        int k = (i >> 2) & (F_ - 1);
        int g = i & 3;
        float v = dwhh[(g * F_ + f) * F_ + k];
        unsigned bits = __float_as_uint(v);
        g_WdecHhDup[f][k][g] = ((u64)bits << 32) | (u64)bits;
    }
    // zero states + counters
    for (int i = tid; i < 2 * 2 * E_ * B_; i += stride) ((float*)g_h)[i] = 0.0f;
    for (int i = tid; i < 2 * F_ * B_; i += stride)     ((float*)g_hd)[i] = 0.0f;
    if (tid < 64) ((unsigned*)g_cnt)[tid] = 0u;
    if (tid < 32) g_cntd[tid] = 0u;
}

// ---------------- xproj GEMM: M=32768, N=2048, K=256 (A dup'd in smem) ----------------
__global__ void __launch_bounds__(256, 1) xproj_gemm(const float* __restrict__ seq)
{
    const int dir = blockIdx.z;
    const int m0 = blockIdx.y * 128;
    const int n0 = blockIdx.x * 128;
    const int tid = threadIdx.x;
    const int ty = tid >> 4;
    const int tx = tid & 15;

    __shared__ u64   As[16][128];
    __shared__ float Bs[16][128];

    u64 acc[8][4];
#pragma unroll
    for (int i = 0; i < 8; i++)
#pragma unroll
        for (int j = 0; j < 4; j++) acc[i][j] = 0ull;

    const float* W = &g_WihIl[dir][0][0];

    for (int k0 = 0; k0 < F_; k0 += 16) {
#pragma unroll
        for (int p = 0; p < 2; p++) {
            int idx = tid + p * 256;
            int row = idx >> 2, kq = idx & 3;
            int m = m0 + row;
            int tt = m >> 6, b = m & 63;
            int ts = dir ? (T_ - 1 - tt) : tt;
            float4 v = *(const float4*)&seq[((size_t)ts * B_ + b) * F_ + k0 + kq * 4];
            As[kq * 4 + 0][row] = dup2(v.x);
            As[kq * 4 + 1][row] = dup2(v.y);
            As[kq * 4 + 2][row] = dup2(v.z);
            As[kq * 4 + 3][row] = dup2(v.w);
        }
#pragma unroll
        for (int p = 0; p < 2; p++) {
            int idx = tid + p * 256;
            int n = idx >> 2, kq = idx & 3;
            float4 v = *(const float4*)&W[(size_t)(n0 + n) * F_ + k0 + kq * 4];
            Bs[kq * 4 + 0][n] = v.x;
            Bs[kq * 4 + 1][n] = v.y;
            Bs[kq * 4 + 2][n] = v.z;
            Bs[kq * 4 + 3][n] = v.w;
        }
        __syncthreads();
#pragma unroll
        for (int kk = 0; kk < 16; kk++) {
            u64 a[8];
#pragma unroll
            for (int i = 0; i < 8; i++) a[i] = As[kk][ty * 8 + i];
            ulonglong2 bA = *(const ulonglong2*)&Bs[kk][tx * 4];
            ulonglong2 bB = *(const ulonglong2*)&Bs[kk][64 + tx * 4];
#pragma unroll
            for (int i = 0; i < 8; i++) {
                fma2(acc[i][0], a[i], bA.x);
                fma2(acc[i][1], a[i], bA.y);
                fma2(acc[i][2], a[i], bB.x);
                fma2(acc[i][3], a[i], bB.y);
            }
        }
        __syncthreads();
    }

    float4 bias0 = *(const float4*)&g_bIl[dir][n0 + tx * 4];
    float4 bias1 = *(const float4*)&g_bIl[dir][n0 + 64 + tx * 4];
    float* out = &g_xproj[0][0][0][0];
#pragma unroll
    for (int i = 0; i < 8; i++) {
        size_t m = (size_t)m0 + ty * 8 + i;
        size_t base = ((size_t)dir * 32768 + m) * (size_t)G4E + n0;
        float2 c0 = unpk(acc[i][0]), c1 = unpk(acc[i][1]);
        float2 c2 = unpk(acc[i][2]), c3 = unpk(acc[i][3]);
        float4 o0 = {c0.x + bias0.x, c0.y + bias0.y, c1.x + bias0.z, c1.y + bias0.w};
        float4 o1 = {c2.x + bias1.x, c2.y + bias1.y, c3.x + bias1.z, c3.y + bias1.w};
        *(float4*)&out[base + tx * 4] = o0;
        *(float4*)&out[base + 64 + tx * 4] = o1;
    }
}

// ---------------- persistent encoder ----------------
// 128 CTAs (64/dir, 8 units each), 256 threads, 4-way k-split.
// h staged into smem via cp.async (each element loaded ONCE per CTA; LDS
// broadcast serves the 8-unit reuse). Transposed xch; red_release barrier.
#define ENC_WS_F4_STRIDE 513   // float4 stride per unit (bank-staggered)
#define ENC_HS_OFF 65664       // 8*513*16 bytes
#define ENC_XCH_OFF (65664 + 131072)
#define ENC_SMEM (ENC_XCH_OFF + 24576)

__global__ void __launch_bounds__(256, 1) enc_persist()
{
    extern __shared__ char smraw[];
    float* ws = (float*)smraw;
    float* hs = (float*)(smraw + ENC_HS_OFF);   // [512][64] floats
    u64*  xch = (u64*)(smraw + ENC_XCH_OFF);    // [3 groups][16 elems][64 slots]

    const int dir = (int)(blockIdx.x >> 6);
    const int u0  = (int)(blockIdx.x & 63) * 8;
    const int tid = threadIdx.x;
    const int ks  = tid >> 6;          // k-quarter 0..3
    const int s   = tid & 63;
    const int l   = tid & 31;
    const int uu  = ((s >> 5) << 2) | (l >> 3);
    const int u   = u0 + uu;
    const int b0  = (l & 7) * 8;

    // load Whh slice once into padded smem
    {
        const float4* src = (const float4*)&g_WhhIl[dir][u0][0][0];
        for (int i = tid; i < 4096; i += 256) {
            int su = i >> 9, kq = i & 511;
            ((float4*)ws)[su * ENC_WS_F4_STRIDE + kq] = src[i];
        }
    }
    __syncthreads();

    const float4* wp4 = (const float4*)ws + uu * ENC_WS_F4_STRIDE;
    unsigned* cnt = &g_cnt[dir][0];
    float c[8];
#pragma unroll
    for (int j = 0; j < 8; j++) c[j] = 0.0f;

    // prefetch xproj for t=0
    float4 xp[8];
    if (ks == 0) {
#pragma unroll
        for (int j = 0; j < 8; j++)
            xp[j] = *(const float4*)&g_xproj[dir][0][b0 + j][u << 2];
    }

    for (int t = 0; t < T_; t++) {
        const int ph = t & 1;

        // wait for h(t-1) from all CTAs of this dir
        if (t > 0) {
            if (tid < 32) {
                const unsigned tgt = (unsigned)t * 64u;
                while (ld_acquire(cnt) < tgt) {}
            }
            __syncthreads();
        }

        const int kbase = ks * 128;

        // stage this group's k-quarter (2048 float4) in 2 pipelined halves
        {
            const float4* hsrc = (const float4*)&g_h[dir][ph][kbase][0];
            float4* hdst = (float4*)&hs[kbase * 64];
            for (int i = s; i < 1024; i += 64) cp16(hdst + i, hsrc + i);
            cp_commit();
            for (int i = s + 1024; i < 2048; i += 64) cp16(hdst + i, hsrc + i);
            cp_commit();
        }

        u64 acc[4][4];
#pragma unroll
        for (int g = 0; g < 4; g++)
#pragma unroll
            for (int p = 0; p < 4; p++) acc[g][p] = 0ull;

#pragma unroll
        for (int half = 0; half < 2; half++) {
            if (half == 0) cp_wait<1>(); else cp_wait<0>();
            bar_named(1 + ks, 64);
            const int kst = kbase + half * 64;
#pragma unroll 4
            for (int kk = 0; kk < 64; kk++) {
                const int k = kst + kk;
                float4 wv = wp4[k];
                u64 wi = dup2(wv.x), wf = dup2(wv.y), wg = dup2(wv.z), wo = dup2(wv.w);
                const ulonglong2* hp = (const ulonglong2*)(hs + k * 64 + b0);
                ulonglong2 hA = hp[0], hB = hp[1];
                fma2(acc[0][0], hA.x, wi); fma2(acc[0][1], hA.y, wi);
                fma2(acc[0][2], hB.x, wi); fma2(acc[0][3], hB.y, wi);
                fma2(acc[1][0], hA.x, wf); fma2(acc[1][1], hA.y, wf);
                fma2(acc[1][2], hB.x, wf); fma2(acc[1][3], hB.y, wf);
                fma2(acc[2][0], hA.x, wg); fma2(acc[2][1], hA.y, wg);
                fma2(acc[2][2], hB.x, wg); fma2(acc[2][3], hB.y, wg);
                fma2(acc[3][0], hA.x, wo); fma2(acc[3][1], hA.y, wo);
                fma2(acc[3][2], hB.x, wo); fma2(acc[3][3], hB.y, wo);
            }
        }

        // publish partials (transposed layout: element-major, slot contiguous)
        if (ks > 0) {
            u64* dst = xch + (size_t)(ks - 1) * 16 * 64 + s;
#pragma unroll
            for (int g = 0; g < 4; g++)
#pragma unroll
                for (int p = 0; p < 4; p++)
                    dst[(g * 4 + p) * 64] = acc[g][p];
        }
        __syncthreads();

        if (ks == 0) {
            const u64* src0 = xch + s;
#pragma unroll
            for (int r = 0; r < 3; r++) {
                const u64* src = src0 + (size_t)r * 16 * 64;
#pragma unroll
                for (int g = 0; g < 4; g++)
#pragma unroll
                    for (int p = 0; p < 4; p++)
                        acc[g][p] = add2(acc[g][p], src[(g * 4 + p) * 64]);
            }
            float iv[8], fv[8], gv[8], ov[8];
#pragma unroll
            for (int p = 0; p < 4; p++) {
                float2 a = unpk(acc[0][p]); iv[2*p] = a.x; iv[2*p+1] = a.y;
                float2 b = unpk(acc[1][p]); fv[2*p] = b.x; fv[2*p+1] = b.y;
                float2 d = unpk(acc[2][p]); gv[2*p] = d.x; gv[2*p+1] = d.y;
                float2 e = unpk(acc[3][p]); ov[2*p] = e.x; ov[2*p+1] = e.y;
            }
            float hv[8];
#pragma unroll
            for (int j = 0; j < 8; j++) {
                float ig = sigm(iv[j] + xp[j].x);
                float fg = sigm(fv[j] + xp[j].y);
                float gg = tanh_f(gv[j] + xp[j].z);
                float og = sigm(ov[j] + xp[j].w);
                c[j] = fg * c[j] + ig * gg;
                hv[j] = og * tanh_f(c[j]);
            }
            float* hout = &g_h[dir][ph ^ 1][u][b0];
            *(float4*)(hout)     = make_float4(hv[0], hv[1], hv[2], hv[3]);
            *(float4*)(hout + 4) = make_float4(hv[4], hv[5], hv[6], hv[7]);
        }
        __syncthreads();

        // arrive, then overlap next-step xproj prefetch with barrier propagation
        if (tid == 0) red_release(cnt, 1u);
        if (ks == 0 && t + 1 < T_) {
#pragma unroll
            for (int j = 0; j < 8; j++)
                xp[j] = *(const float4*)&g_xproj[dir][t + 1][b0 + j][u << 2];
        }
    }
}

// ---------------- persistent decoder (xp0 fused) ----------------
// 128 CTAs (2 f-units each), 256 threads, 4-way k-split; h via ld.global.cg
// (only 2x redundancy - not the binding pipe here).
#define DEC_XCH_OFF 16384
#define DEC_XP0_OFF (16384 + 6144)
#define DEC_SMEM (DEC_XP0_OFF + 2048)

__global__ void __launch_bounds__(256, 1) dec_persist(float* __restrict__ out)
{
    extern __shared__ char smraw[];
    u64*   wsd  = (u64*)smraw;                      // [2][256][4] u64
    u64*   xch  = (u64*)(smraw + DEC_XCH_OFF);      // [3][4][64] u64
    float* xp0s = (float*)(smraw + DEC_XP0_OFF);    // [64][2][4] floats

    const int tid = threadIdx.x;
    const int ks  = tid >> 6;          // k-quarter 0..3 (64 k each)
    const int s   = tid & 63;
    const int l   = tid & 31;
    const int uu  = s >> 5;            // unit within CTA (warp-uniform)
    const int b0  = l * 2;
    const int f   = (int)blockIdx.x * 2 + uu;

    // load duplicated dec Whh slice once
    {
        const float4* src = (const float4*)&g_WdecHhDup[blockIdx.x * 2][0][0];
        float4* dst = (float4*)wsd;
        for (int i = tid; i < 1024; i += 256) dst[i] = src[i];
    }

    // ---- fused xp0: thread = (f_local, gate-pair, batch) ----
    {
        const int fl = tid >> 7;            // 0..1
        const int gp = (tid >> 6) & 1;      // gate pair: 0 -> (i,f), 1 -> (g,o)
        const int b  = tid & 63;
        const int ff = (int)blockIdx.x * 2 + fl;
        float a0 = 0.0f, a1 = 0.0f;
        const float* wih = &g_WdecIhIl[ff][0][gp * 2];
#pragma unroll 4
        for (int k = 0; k < 512; k++) {
            float hv = __ldg(&g_h[0][0][k][b]);
            float2 w2 = *(const float2*)&wih[k * 4];
            a0 += hv * w2.x; a1 += hv * w2.y;
        }
#pragma unroll 4
        for (int k = 0; k < 512; k++) {
            float hv = __ldg(&g_h[1][0][k][b]);
            float2 w2 = *(const float2*)&wih[(512 + k) * 4];
            a0 += hv * w2.x; a1 += hv * w2.y;
        }
        xp0s[(b * 2 + fl) * 4 + gp * 2 + 0] = a0 + g_bdecIl[ff][gp * 2 + 0];
        xp0s[(b * 2 + fl) * 4 + gp * 2 + 1] = a1 + g_bdecIl[ff][gp * 2 + 1];
    }
    __syncthreads();

    const u64* wp = wsd + uu * 1024;   // [k][4]
    unsigned* cnt = g_cntd;
    float c0 = 0.f, c1 = 0.f;
    float4 xpA, xpB;
    if (ks == 0) {
        xpA = *(const float4*)&xp0s[(b0 * 2 + uu) * 4];
        xpB = *(const float4*)&xp0s[((b0 + 1) * 2 + uu) * 4];
    }

    for (int t = 0; t < T_; t++) {
        const int ph = t & 1;

        if (t > 0) {
            if (tid < 32) {
                const unsigned tgt = (unsigned)t * 128u;
                while (ld_acquire(cnt) < tgt) {}
            }
            __syncthreads();
        }

        const float* hbase = &g_hd[ph][0][0];
        const int kbase = ks * 64;

        u64 acc[4] = {0ull, 0ull, 0ull, 0ull};
#pragma unroll 8
        for (int kk = 0; kk < 64; kk++) {
            const int k = kbase + kk;
            u64 h01 = ldcg8(hbase + k * 64 + b0);
            const ulonglong2* wq = (const ulonglong2*)(wp + k * 4);
            ulonglong2 w_if = wq[0], w_go = wq[1];
            fma2(acc[0], h01, w_if.x);
            fma2(acc[1], h01, w_if.y);
            fma2(acc[2], h01, w_go.x);
            fma2(acc[3], h01, w_go.y);
        }

        if (ks > 0) {
            u64* dst = xch + (size_t)(ks - 1) * 4 * 64 + s;
            dst[0]       = acc[0];
            dst[64]      = acc[1];
            dst[128]     = acc[2];
            dst[192]     = acc[3];
        }
        __syncthreads();

        if (ks == 0) {
            const u64* src0 = xch + s;
#pragma unroll
            for (int r = 0; r < 3; r++) {
                const u64* src = src0 + (size_t)r * 4 * 64;
                acc[0] = add2(acc[0], src[0]);
                acc[1] = add2(acc[1], src[64]);
                acc[2] = add2(acc[2], src[128]);
                acc[3] = add2(acc[3], src[192]);
            }
            float2 iv = unpk(acc[0]), fv = unpk(acc[1]);
            float2 gv = unpk(acc[2]), ov = unpk(acc[3]);
            float2 hv;
            { float ig = sigm(iv.x + xpA.x), fg = sigm(fv.x + xpA.y);
              float gg = tanh_f(gv.x + xpA.z), og = sigm(ov.x + xpA.w);
              c0 = fg * c0 + ig * gg; hv.x = og * tanh_f(c0); }
            { float ig = sigm(iv.y + xpB.x), fg = sigm(fv.y + xpB.y);
              float gg = tanh_f(gv.y + xpB.z), og = sigm(ov.y + xpB.w);
              c1 = fg * c1 + ig * gg; hv.y = og * tanh_f(c1); }
            *(float2*)&g_hd[ph ^ 1][f][b0] = hv;
            out[((size_t)t * B_ + b0 + 0) * F_ + f] = hv.x;
            out[((size_t)t * B_ + b0 + 1) * F_ + f] = hv.y;
        }
        __syncthreads();

        if (tid == 0) red_release(cnt, 1u);
    }
}

// ---------------- launch ----------------
extern "C" void kernel_launch(void* const* d_in, const int* in_sizes, int n_in,
                              void* d_out, int out_size)
{
    const float* seq  = (const float*)d_in[0];
    const float* wihf = (const float*)d_in[1];
    const float* whhf = (const float*)d_in[2];
    const float* bf   = (const float*)d_in[3];
    const float* wihb = (const float*)d_in[4];
    const float* whhb = (const float*)d_in[5];
    const float* bb   = (const float*)d_in[6];
    const float* dwih = (const float*)d_in[7];
    const float* dwhh = (const float*)d_in[8];
    const float* db   = (const float*)d_in[9];
    float* out = (float*)d_out;

    cudaFuncSetAttribute(enc_persist, cudaFuncAttributeMaxDynamicSharedMemorySize, ENC_SMEM);
    cudaFuncSetAttribute(dec_persist, cudaFuncAttributeMaxDynamicSharedMemorySize, DEC_SMEM);

    probe_kernel<<<1, 1>>>();

    prep_kernel<<<1024, 256>>>(wihf, whhf, bf, wihb, whhb, bb, dwih, dwhh, db);

    dim3 g(G4E / 128, 32768 / 128, 2);
    xproj_gemm<<<g, 256>>>(seq);

    enc_persist<<<128, 256, ENC_SMEM>>>();

    dec_persist<<<128, 256, DEC_SMEM>>>(out);
}

// round 12
// speedup vs baseline: 1.7262x; 1.1525x over previous
#include <cuda_runtime.h>
#include <math.h>

// Problem dims
#define T_    512
#define B_    64
#define F_    256
#define E_    512
#define G4E   2048   // 4*E
#define G4F   1024   // 4*F
#define DECIN 1024   // 2*E

typedef unsigned long long u64;

// ---------------- device scratch (static; no allocations) ----------------
__device__ float g_xproj[2][T_][B_][G4E];     // [dir][t][b][col], col = u*4+gate
__device__ float g_WihIl[2][G4E][F_];         // interleaved enc Wih (rows = u*4+g)
__device__ float g_bIl[2][G4E];
__device__ float g_WhhIl[2][E_][E_][4];       // [dir][u][k][gate]
__device__ float g_h[2][2][E_][B_];           // [dir][phase][u][b]  ping-pong
__device__ float g_WdecIhIl[F_][DECIN][4];    // [f][k][gate]
__device__ float g_bdecIl[F_][4];
__device__ u64   g_WdecHhDup[F_][F_][4];      // [f][k][gate] duplicated {w,w}
__device__ float g_hd[2][F_][B_];             // decoder h ping-pong
__device__ unsigned g_cnt[2][32];             // enc barrier counters (padded per dir)
__device__ unsigned g_cntd[32];               // dec barrier counter

__device__ __forceinline__ float sigm(float x) {
    return __fdividef(1.0f, 1.0f + __expf(-x));
}
__device__ __forceinline__ float tanh_f(float x) {
    float ax = fabsf(x);
    float e = __expf(-2.0f * ax);
    float r = (1.0f - e) * __fdividef(1.0f, 1.0f + e);
    return copysignf(r, x);
}

__device__ __forceinline__ u64 dup2(float x) {
    u64 r; asm("mov.b64 %0, {%1, %1};" : "=l"(r) : "f"(x)); return r;
}
__device__ __forceinline__ void fma2(u64& d, u64 a, u64 b) {
    asm("fma.rn.f32x2 %0, %1, %2, %0;" : "+l"(d) : "l"(a), "l"(b));
}
__device__ __forceinline__ u64 add2(u64 a, u64 b) {
    u64 r; asm("add.rn.f32x2 %0, %1, %2;" : "=l"(r) : "l"(a), "l"(b)); return r;
}
__device__ __forceinline__ float2 unpk(u64 v) {
    float2 r; asm("mov.b64 {%0, %1}, %2;" : "=f"(r.x), "=f"(r.y) : "l"(v)); return r;
}
__device__ __forceinline__ unsigned ld_acquire(unsigned* p) {
    unsigned v;
    asm volatile("ld.acquire.gpu.global.u32 %0, [%1];" : "=r"(v) : "l"(p) : "memory");
    return v;
}
__device__ __forceinline__ void red_release(unsigned* p, unsigned v) {
    asm volatile("red.release.gpu.global.add.u32 [%0], %1;" :: "l"(p), "r"(v) : "memory");
}
__device__ __forceinline__ u64 ldcg8(const void* p) {
    u64 v;
    asm volatile("ld.global.cg.u64 %0, [%1];" : "=l"(v) : "l"(p));
    return v;
}
__device__ __forceinline__ void cp16(void* sdst, const void* gsrc) {
    unsigned s = (unsigned)__cvta_generic_to_shared(sdst);
    asm volatile("cp.async.cg.shared.global [%0], [%1], 16;" :: "r"(s), "l"(gsrc) : "memory");
}
__device__ __forceinline__ void cp_commit() { asm volatile("cp.async.commit_group;" ::: "memory"); }
template<int N> __device__ __forceinline__ void cp_wait() {
    asm volatile("cp.async.wait_group %0;" :: "n"(N) : "memory");
}

// ---------------- probe: keeps ncu's captured position on enc_persist ----------------
__global__ void probe_kernel() {}

// ---------------- prep: interleave weights, zero states ----------------
__global__ void prep_kernel(const float* wihf, const float* whhf, const float* bf,
                            const float* wihb, const float* whhb, const float* bb,
                            const float* dwih, const float* dwhh, const float* db)
{
    int tid = blockIdx.x * blockDim.x + threadIdx.x;
    int stride = gridDim.x * blockDim.x;

    // enc Wih interleave: [2][2048][256]
    for (int i = tid; i < 2 * G4E * F_; i += stride) {
        int d = i / (G4E * F_);
        int r = i - d * (G4E * F_);
        int col = r / F_;
        int k = r - col * F_;
        int u = col >> 2, g = col & 3;
        const float* src = d ? wihb : wihf;
        g_WihIl[d][col][k] = src[(g * E_ + u) * F_ + k];
    }
    // enc bias interleave
    for (int i = tid; i < 2 * G4E; i += stride) {
        int d = i >> 11, col = i & (G4E - 1);
        int u = col >> 2, g = col & 3;
        g_bIl[d][col] = (d ? bb : bf)[g * E_ + u];
    }
    // enc Whh interleave: [2][512][512][4]
    for (int i = tid; i < 2 * E_ * E_ * 4; i += stride) {
        int d = i / (E_ * E_ * 4);
        int r = i - d * (E_ * E_ * 4);
        int u = r / (E_ * 4);
        int k = (r >> 2) & (E_ - 1);
        int g = r & 3;
        g_WhhIl[d][u][k][g] = (d ? whhb : whhf)[(g * E_ + u) * E_ + k];
    }
    // dec Wih interleave: [256][1024][4]
    for (int i = tid; i < F_ * DECIN * 4; i += stride) {
        int f = i / (DECIN * 4);
        int k = (i >> 2) & (DECIN - 1);
        int g = i & 3;
        g_WdecIhIl[f][k][g] = dwih[(g * F_ + f) * DECIN + k];
    }
    for (int i = tid; i < G4F; i += stride) {
        int f = i >> 2, g = i & 3;
        g_bdecIl[f][g] = db[g * F_ + f];
    }
    // dec Whh duplicated: [256][256][4] u64
    for (int i = tid; i < F_ * F_ * 4; i += stride) {
        int f = i / (F_ * 4);
        int k = (i >> 2) & (F_ - 1);
        int g = i & 3;
        float v = dwhh[(g * F_ + f) * F_ + k];
        unsigned bits = __float_as_uint(v);
        g_WdecHhDup[f][k][g] = ((u64)bits << 32) | (u64)bits;
    }
    // zero states + counters
    for (int i = tid; i < 2 * 2 * E_ * B_; i += stride) ((float*)g_h)[i] = 0.0f;
    for (int i = tid; i < 2 * F_ * B_; i += stride)     ((float*)g_hd)[i] = 0.0f;
    if (tid < 64) ((unsigned*)g_cnt)[tid] = 0u;
    if (tid < 32) g_cntd[tid] = 0u;
}

// ---------------- xproj GEMM: M=32768, N=2048, K=256 ----------------
// As stored PLAIN float (2 LDS.128/thread/kk), dup at use via MOVs: halves L1 wavefronts.
__global__ void __launch_bounds__(256, 1) xproj_gemm(const float* __restrict__ seq)
{
    const int dir = blockIdx.z;
    const int m0 = blockIdx.y * 128;
    const int n0 = blockIdx.x * 128;
    const int tid = threadIdx.x;
    const int ty = tid >> 4;
    const int tx = tid & 15;

    __shared__ float As[16][128];
    __shared__ float Bs[16][128];

    u64 acc[8][4];
#pragma unroll
    for (int i = 0; i < 8; i++)
#pragma unroll
        for (int j = 0; j < 4; j++) acc[i][j] = 0ull;

    const float* W = &g_WihIl[dir][0][0];

    for (int k0 = 0; k0 < F_; k0 += 16) {
#pragma unroll
        for (int p = 0; p < 2; p++) {
            int idx = tid + p * 256;
            int row = idx >> 2, kq = idx & 3;
            int m = m0 + row;
            int tt = m >> 6, b = m & 63;
            int ts = dir ? (T_ - 1 - tt) : tt;
            float4 v = *(const float4*)&seq[((size_t)ts * B_ + b) * F_ + k0 + kq * 4];
            As[kq * 4 + 0][row] = v.x;
            As[kq * 4 + 1][row] = v.y;
            As[kq * 4 + 2][row] = v.z;
            As[kq * 4 + 3][row] = v.w;
        }
#pragma unroll
        for (int p = 0; p < 2; p++) {
            int idx = tid + p * 256;
            int n = idx >> 2, kq = idx & 3;
            float4 v = *(const float4*)&W[(size_t)(n0 + n) * F_ + k0 + kq * 4];
            Bs[kq * 4 + 0][n] = v.x;
            Bs[kq * 4 + 1][n] = v.y;
            Bs[kq * 4 + 2][n] = v.z;
            Bs[kq * 4 + 3][n] = v.w;
        }
        __syncthreads();
#pragma unroll
        for (int kk = 0; kk < 16; kk++) {
            float4 a0 = *(const float4*)&As[kk][ty * 8];
            float4 a1 = *(const float4*)&As[kk][ty * 8 + 4];
            ulonglong2 bA = *(const ulonglong2*)&Bs[kk][tx * 4];
            ulonglong2 bB = *(const ulonglong2*)&Bs[kk][64 + tx * 4];
            float av[8] = {a0.x, a0.y, a0.z, a0.w, a1.x, a1.y, a1.z, a1.w};
#pragma unroll
            for (int i = 0; i < 8; i++) {
                u64 ad = dup2(av[i]);
                fma2(acc[i][0], ad, bA.x);
                fma2(acc[i][1], ad, bA.y);
                fma2(acc[i][2], ad, bB.x);
                fma2(acc[i][3], ad, bB.y);
            }
        }
        __syncthreads();
    }

    float4 bias0 = *(const float4*)&g_bIl[dir][n0 + tx * 4];
    float4 bias1 = *(const float4*)&g_bIl[dir][n0 + 64 + tx * 4];
    float* out = &g_xproj[0][0][0][0];
#pragma unroll
    for (int i = 0; i < 8; i++) {
        size_t m = (size_t)m0 + ty * 8 + i;
        size_t base = ((size_t)dir * 32768 + m) * (size_t)G4E + n0;
        float2 c0 = unpk(acc[i][0]), c1 = unpk(acc[i][1]);
        float2 c2 = unpk(acc[i][2]), c3 = unpk(acc[i][3]);
        float4 o0 = {c0.x + bias0.x, c0.y + bias0.y, c1.x + bias0.z, c1.y + bias0.w};
        float4 o1 = {c2.x + bias1.x, c2.y + bias1.y, c3.x + bias1.z, c3.y + bias1.w};
        *(float4*)&out[base + tx * 4] = o0;
        *(float4*)&out[base + 64 + tx * 4] = o1;
    }
}

// ---------------- persistent encoder ----------------
// 128 CTAs (64/dir, 8 units each), 128 threads = 4 warps; warp = k-quarter.
// Thread: 2 units x 8 batches (64 MACs/k from 4 LDS.128) -> L1 wavefronts ~= fma floor.
// Weights k-major [k][8u] float4 (conflict-free rows). xproj staged via cp.async.
#define ENC_HS_OFF  65536                    // ws: 512*8 float4 = 64KB
#define ENC_XCH_OFF (65536 + 131072)         // hs: 512*64 floats = 128KB
#define ENC_XPS_OFF (ENC_XCH_OFF + 24576)    // xch: u64[3][32][32] = 24KB
#define ENC_SMEM    (ENC_XPS_OFF + 8192)     // xps: float4[64][8] = 8KB -> 229376

__global__ void __launch_bounds__(128, 1) enc_persist()
{
    extern __shared__ char smraw[];
    float4* wsP = (float4*)smraw;                    // [k][8 units]
    float*  hs  = (float*)(smraw + ENC_HS_OFF);      // [512][64]
    u64*    xch = (u64*)(smraw + ENC_XCH_OFF);       // [3][32 elems][32 lanes]
    float4* xps = (float4*)(smraw + ENC_XPS_OFF);    // [64 b][8 u]

    const int dir = (int)(blockIdx.x >> 6);
    const int u0  = (int)(blockIdx.x & 63) * 8;
    const int tid = threadIdx.x;
    const int ks  = tid >> 5;          // warp = k-quarter 0..3
    const int l   = tid & 31;
    const int ug  = l >> 3;            // unit-pair group 0..3
    const int ua  = ug * 2;            // local units ua, ua+1
    const int b0  = (l & 7) * 8;       // 8 batches

    // load Whh slice once, transposed to k-major [k][u]
    {
        const float4* src = (const float4*)&g_WhhIl[dir][u0][0][0];
        for (int i = tid; i < 4096; i += 128)
            wsP[i] = src[(i & 7) * 512 + (i >> 3)];
    }
    __syncthreads();

    unsigned* cnt = &g_cnt[dir][0];
    float c[2][8];
#pragma unroll
    for (int ul = 0; ul < 2; ul++)
#pragma unroll
        for (int j = 0; j < 8; j++) c[ul][j] = 0.0f;

    // stage xproj for t=0
    for (int i = tid; i < 512; i += 128)
        cp16(&xps[i], &g_xproj[dir][0][i >> 3][(u0 + (i & 7)) << 2]);
    cp_commit();

    for (int t = 0; t < T_; t++) {
        const int ph = t & 1;

        // wait for h(t-1) from all CTAs of this dir
        if (t > 0) {
            if (tid < 32) {
                const unsigned tgt = (unsigned)t * 64u;
                while (ld_acquire(cnt) < tgt) {}
            }
            __syncthreads();
        }

        const int kbase = ks * 128;

        // stage this warp's k-quarter (2048 float4) in 2 pipelined halves
        {
            const float4* hsrc = (const float4*)&g_h[dir][ph][kbase][0];
            float4* hdst = (float4*)&hs[kbase * 64];
            for (int i = l; i < 1024; i += 32) cp16(hdst + i, hsrc + i);
            cp_commit();
            for (int i = l + 1024; i < 2048; i += 32) cp16(hdst + i, hsrc + i);
            cp_commit();
        }
        // pending groups now: [xps][h1][h2]

        u64 acc[2][4][4];
#pragma unroll
        for (int ul = 0; ul < 2; ul++)
#pragma unroll
            for (int g = 0; g < 4; g++)
#pragma unroll
                for (int p = 0; p < 4; p++) acc[ul][g][p] = 0ull;

#pragma unroll
        for (int half = 0; half < 2; half++) {
            if (half == 0) cp_wait<1>(); else cp_wait<0>();
            __syncwarp();
            const int kst = kbase + half * 64;
#pragma unroll 4
            for (int kk = 0; kk < 64; kk++) {
                const int k = kst + kk;
                const float4* wrow = wsP + k * 8;
                float4 wa = wrow[ua];
                float4 wb = wrow[ua + 1];
                const ulonglong2* hp = (const ulonglong2*)(hs + k * 64 + b0);
                ulonglong2 hA = hp[0], hB = hp[1];
                u64 d0 = dup2(wa.x), d1 = dup2(wa.y), d2 = dup2(wa.z), d3 = dup2(wa.w);
                fma2(acc[0][0][0], hA.x, d0); fma2(acc[0][0][1], hA.y, d0);
                fma2(acc[0][0][2], hB.x, d0); fma2(acc[0][0][3], hB.y, d0);
                fma2(acc[0][1][0], hA.x, d1); fma2(acc[0][1][1], hA.y, d1);
                fma2(acc[0][1][2], hB.x, d1); fma2(acc[0][1][3], hB.y, d1);
                fma2(acc[0][2][0], hA.x, d2); fma2(acc[0][2][1], hA.y, d2);
                fma2(acc[0][2][2], hB.x, d2); fma2(acc[0][2][3], hB.y, d2);
                fma2(acc[0][3][0], hA.x, d3); fma2(acc[0][3][1], hA.y, d3);
                fma2(acc[0][3][2], hB.x, d3); fma2(acc[0][3][3], hB.y, d3);
                u64 e0 = dup2(wb.x), e1 = dup2(wb.y), e2 = dup2(wb.z), e3 = dup2(wb.w);
                fma2(acc[1][0][0], hA.x, e0); fma2(acc[1][0][1], hA.y, e0);
                fma2(acc[1][0][2], hB.x, e0); fma2(acc[1][0][3], hB.y, e0);
                fma2(acc[1][1][0], hA.x, e1); fma2(acc[1][1][1], hA.y, e1);
                fma2(acc[1][1][2], hB.x, e1); fma2(acc[1][1][3], hB.y, e1);
                fma2(acc[1][2][0], hA.x, e2); fma2(acc[1][2][1], hA.y, e2);
                fma2(acc[1][2][2], hB.x, e2); fma2(acc[1][2][3], hB.y, e2);
                fma2(acc[1][3][0], hA.x, e3); fma2(acc[1][3][1], hA.y, e3);
                fma2(acc[1][3][2], hB.x, e3); fma2(acc[1][3][3], hB.y, e3);
            }
        }

        // publish partials (transposed: element-major, lane contiguous)
        if (ks > 0) {
            u64* dst = xch + (size_t)(ks - 1) * 32 * 32 + l;
#pragma unroll
            for (int ul = 0; ul < 2; ul++)
#pragma unroll
                for (int g = 0; g < 4; g++)
#pragma unroll
                    for (int p = 0; p < 4; p++)
                        dst[(ul * 16 + g * 4 + p) * 32] = acc[ul][g][p];
        }
        __syncthreads();

        if (ks == 0) {
            const u64* src0 = xch + l;
#pragma unroll
            for (int r = 0; r < 3; r++) {
                const u64* src = src0 + (size_t)r * 32 * 32;
#pragma unroll
                for (int ul = 0; ul < 2; ul++)
#pragma unroll
                    for (int g = 0; g < 4; g++)
#pragma unroll
                        for (int p = 0; p < 4; p++)
                            acc[ul][g][p] = add2(acc[ul][g][p], src[(ul * 16 + g * 4 + p) * 32]);
            }
#pragma unroll
            for (int ul = 0; ul < 2; ul++) {
                const int u = ua + ul;
                float hv[8];
#pragma unroll
                for (int p = 0; p < 4; p++) {
                    float2 iv = unpk(acc[ul][0][p]);
                    float2 fv = unpk(acc[ul][1][p]);
                    float2 gv = unpk(acc[ul][2][p]);
                    float2 ov = unpk(acc[ul][3][p]);
#pragma unroll
                    for (int q = 0; q < 2; q++) {
                        int j = p * 2 + q;
                        float4 xv = xps[(b0 + j) * 8 + u];
                        float iq = q ? iv.y : iv.x;
                        float fq = q ? fv.y : fv.x;
                        float gq = q ? gv.y : gv.x;
                        float oq = q ? ov.y : ov.x;
                        float ig = sigm(iq + xv.x);
                        float fg = sigm(fq + xv.y);
                        float gg = tanh_f(gq + xv.z);
                        float og = sigm(oq + xv.w);
                        c[ul][j] = fg * c[ul][j] + ig * gg;
                        hv[j] = og * tanh_f(c[ul][j]);
                    }
                }
                float* hout = &g_h[dir][ph ^ 1][u0 + u][b0];
                *(float4*)(hout)     = make_float4(hv[0], hv[1], hv[2], hv[3]);
                *(float4*)(hout + 4) = make_float4(hv[4], hv[5], hv[6], hv[7]);
            }
        }
        __syncthreads();

        // arrive; then stage next step's xproj (independent of barrier)
        if (tid == 0) red_release(cnt, 1u);
        if (t + 1 < T_) {
            for (int i = tid; i < 512; i += 128)
                cp16(&xps[i], &g_xproj[dir][t + 1][i >> 3][(u0 + (i & 7)) << 2]);
            cp_commit();
        }
    }
}

// ---------------- persistent decoder (xp0 fused) ----------------
#define DEC_XCH_OFF 16384
#define DEC_XP0_OFF (16384 + 6144)
#define DEC_SMEM (DEC_XP0_OFF + 2048)

__global__ void __launch_bounds__(256, 1) dec_persist(float* __restrict__ out)
{
    extern __shared__ char smraw[];
    u64*   wsd  = (u64*)smraw;                      // [2][256][4] u64
    u64*   xch  = (u64*)(smraw + DEC_XCH_OFF);      // [3][4][64] u64
    float* xp0s = (float*)(smraw + DEC_XP0_OFF);    // [64][2][4] floats

    const int tid = threadIdx.x;
    const int ks  = tid >> 6;          // k-quarter 0..3 (64 k each)
    const int s   = tid & 63;
    const int l   = tid & 31;
    const int uu  = s >> 5;            // unit within CTA (warp-uniform)
    const int b0  = l * 2;
    const int f   = (int)blockIdx.x * 2 + uu;

    // load duplicated dec Whh slice once
    {
        const float4* src = (const float4*)&g_WdecHhDup[blockIdx.x * 2][0][0];
        float4* dst = (float4*)wsd;
        for (int i = tid; i < 1024; i += 256) dst[i] = src[i];
    }

    // ---- fused xp0 ----
    {
        const int fl = tid >> 7;
        const int gp = (tid >> 6) & 1;
        const int b  = tid & 63;
        const int ff = (int)blockIdx.x * 2 + fl;
        float a0 = 0.0f, a1 = 0.0f;
        const float* wih = &g_WdecIhIl[ff][0][gp * 2];
#pragma unroll 4
        for (int k = 0; k < 512; k++) {
            float hv = __ldg(&g_h[0][0][k][b]);
            float2 w2 = *(const float2*)&wih[k * 4];
            a0 += hv * w2.x; a1 += hv * w2.y;
        }
#pragma unroll 4
        for (int k = 0; k < 512; k++) {
            float hv = __ldg(&g_h[1][0][k][b]);
            float2 w2 = *(const float2*)&wih[(512 + k) * 4];
            a0 += hv * w2.x; a1 += hv * w2.y;
        }
        xp0s[(b * 2 + fl) * 4 + gp * 2 + 0] = a0 + g_bdecIl[ff][gp * 2 + 0];
        xp0s[(b * 2 + fl) * 4 + gp * 2 + 1] = a1 + g_bdecIl[ff][gp * 2 + 1];
    }
    __syncthreads();

    const u64* wp = wsd + uu * 1024;
    unsigned* cnt = g_cntd;
    float c0 = 0.f, c1 = 0.f;
    float4 xpA, xpB;
    if (ks == 0) {
        xpA = *(const float4*)&xp0s[(b0 * 2 + uu) * 4];
        xpB = *(const float4*)&xp0s[((b0 + 1) * 2 + uu) * 4];
    }

    for (int t = 0; t < T_; t++) {
        const int ph = t & 1;

        if (t > 0) {
            if (tid < 32) {
                const unsigned tgt = (unsigned)t * 128u;
                while (ld_acquire(cnt) < tgt) {}
            }
            __syncthreads();
        }

        const float* hbase = &g_hd[ph][0][0];
        const int kbase = ks * 64;

        u64 acc[4] = {0ull, 0ull, 0ull, 0ull};
#pragma unroll 8
        for (int kk = 0; kk < 64; kk++) {
            const int k = kbase + kk;
            u64 h01 = ldcg8(hbase + k * 64 + b0);
            const ulonglong2* wq = (const ulonglong2*)(wp + k * 4);
            ulonglong2 w_if = wq[0], w_go = wq[1];
            fma2(acc[0], h01, w_if.x);
            fma2(acc[1], h01, w_if.y);
            fma2(acc[2], h01, w_go.x);
            fma2(acc[3], h01, w_go.y);
        }

        if (ks > 0) {
            u64* dst = xch + (size_t)(ks - 1) * 4 * 64 + s;
            dst[0]   = acc[0];
            dst[64]  = acc[1];
            dst[128] = acc[2];
            dst[192] = acc[3];
        }
        __syncthreads();

        if (ks == 0) {
            const u64* src0 = xch + s;
#pragma unroll
            for (int r = 0; r < 3; r++) {
                const u64* src = src0 + (size_t)r * 4 * 64;
                acc[0] = add2(acc[0], src[0]);
                acc[1] = add2(acc[1], src[64]);
                acc[2] = add2(acc[2], src[128]);
                acc[3] = add2(acc[3], src[192]);
            }
            float2 iv = unpk(acc[0]), fv = unpk(acc[1]);
            float2 gv = unpk(acc[2]), ov = unpk(acc[3]);
            float2 hv;
            { float ig = sigm(iv.x + xpA.x), fg = sigm(fv.x + xpA.y);
              float gg = tanh_f(gv.x + xpA.z), og = sigm(ov.x + xpA.w);
              c0 = fg * c0 + ig * gg; hv.x = og * tanh_f(c0); }
            { float ig = sigm(iv.y + xpB.x), fg = sigm(fv.y + xpB.y);
              float gg = tanh_f(gv.y + xpB.z), og = sigm(ov.y + xpB.w);
              c1 = fg * c1 + ig * gg; hv.y = og * tanh_f(c1); }
            *(float2*)&g_hd[ph ^ 1][f][b0] = hv;
            out[((size_t)t * B_ + b0 + 0) * F_ + f] = hv.x;
            out[((size_t)t * B_ + b0 + 1) * F_ + f] = hv.y;
        }
        __syncthreads();

        if (tid == 0) red_release(cnt, 1u);
    }
}

// ---------------- launch ----------------
extern "C" void kernel_launch(void* const* d_in, const int* in_sizes, int n_in,
                              void* d_out, int out_size)
{
    const float* seq  = (const float*)d_in[0];
    const float* wihf = (const float*)d_in[1];
    const float* whhf = (const float*)d_in[2];
    const float* bf   = (const float*)d_in[3];
    const float* wihb = (const float*)d_in[4];
    const float* whhb = (const float*)d_in[5];
    const float* bb   = (const float*)d_in[6];
    const float* dwih = (const float*)d_in[7];
    const float* dwhh = (const float*)d_in[8];
    const float* db   = (const float*)d_in[9];
    float* out = (float*)d_out;

    cudaFuncSetAttribute(enc_persist, cudaFuncAttributeMaxDynamicSharedMemorySize, ENC_SMEM);
    cudaFuncSetAttribute(dec_persist, cudaFuncAttributeMaxDynamicSharedMemorySize, DEC_SMEM);

    probe_kernel<<<1, 1>>>();

    prep_kernel<<<1024, 256>>>(wihf, whhf, bf, wihb, whhb, bb, dwih, dwhh, db);

    dim3 g(G4E / 128, 32768 / 128, 2);
    xproj_gemm<<<g, 256>>>(seq);

    enc_persist<<<128, 128, ENC_SMEM>>>();

    dec_persist<<<128, 256, DEC_SMEM>>>(out);
}